// round 2
// baseline (speedup 1.0000x reference)
#include <cuda_runtime.h>
#include <cstdint>
#include <cstddef>

#define BATCH 4
#define CH    256
#define CKD   32
#define NPIX  4096
#define HWD   64

// ---------------- scratch (static __device__ — no allocation allowed) ----------------
__device__ float g_q1[BATCH*CKD*NPIX];
__device__ float g_k1[BATCH*CKD*NPIX];
__device__ float g_q2[BATCH*CKD*NPIX];
__device__ float g_k2[BATCH*CKD*NPIX];
__device__ float g_v1[BATCH*CH*NPIX];
__device__ float g_v2[BATCH*CH*NPIX];
__device__ float g_d1[BATCH*CH*NPIX];   // conv1x1(x1, wd1)
__device__ float g_d2[BATCH*CH*NPIX];   // conv1x1(x2, wd1)
__device__ float g_c31[BATCH*CH*NPIX];  // conv3x3(x1, wd3)
__device__ float g_c32[BATCH*CH*NPIX];  // conv3x3(x2, wd3)
__device__ float g_wd3t[CH*9*CH];       // wd3 transposed to [c][kk][o]
__device__ float g_attn1[(size_t)BATCH*NPIX*NPIX];  // 256 MB
__device__ float g_attn2[(size_t)BATCH*NPIX*NPIX];  // 256 MB

// ---------------- fast exp (poly exp2, rel err ~3e-5; avoids MUFU bottleneck) --------
__device__ __forceinline__ float fast_exp(float x) {
    // x <= 0 here (post max-subtraction)
    float t = x * 1.4426950408889634f;
    t = fmaxf(t, -126.0f);
    float n = floorf(t);
    float f = t - n;
    float p = 1.5403530393e-4f;
    p = fmaf(p, f, 1.3333558146e-3f);
    p = fmaf(p, f, 9.6181291076e-3f);
    p = fmaf(p, f, 5.5504108665e-2f);
    p = fmaf(p, f, 2.4022650696e-1f);
    p = fmaf(p, f, 6.9314718056e-1f);
    p = fmaf(p, f, 1.0f);
    float s = __int_as_float(((int)n + 127) << 23);
    return p * s;
}

// ---------------- 1x1 conv / projection GEMM -----------------------------------------
// Y[b][m][n] = sum_c W[m][c] * X[b][c][n] + bias[m]
template<int BM, int BN, int BK, int TM, int TN>
__global__ __launch_bounds__((BM/TM)*(BN/TN))
void proj_gemm(const float* __restrict__ W, const float* __restrict__ bias,
               const float* __restrict__ X, float* __restrict__ Y,
               int M, int C, int N)
{
    constexpr int NT = (BM/TM)*(BN/TN);
    __shared__ float sW[BK][BM+1];
    __shared__ float sX[BK][BN];
    const int tid = threadIdx.x;
    const int b = blockIdx.z;
    const int m0 = blockIdx.y*BM, n0 = blockIdx.x*BN;
    const float* Xb = X + (size_t)b*C*N;

    float acc[TM][TN];
    #pragma unroll
    for (int i=0;i<TM;i++)
        #pragma unroll
        for (int j=0;j<TN;j++) acc[i][j] = 0.f;

    const int tx = tid % (BN/TN), ty = tid / (BN/TN);

    for (int k0 = 0; k0 < C; k0 += BK) {
        #pragma unroll
        for (int idx = tid; idx < BM*BK; idx += NT) {
            int mm = idx / BK, kk = idx % BK;
            sW[kk][mm] = W[(size_t)(m0+mm)*C + k0 + kk];
        }
        #pragma unroll
        for (int idx = tid; idx < BN*BK; idx += NT) {
            int kk = idx / BN, nn = idx % BN;
            sX[kk][nn] = Xb[(size_t)(k0+kk)*N + n0 + nn];
        }
        __syncthreads();
        #pragma unroll
        for (int kk=0;kk<BK;kk++){
            float a[TM], bb[TN];
            #pragma unroll
            for (int i=0;i<TM;i++) a[i] = sW[kk][ty*TM+i];
            #pragma unroll
            for (int j=0;j<TN;j++) bb[j] = sX[kk][tx*TN+j];
            #pragma unroll
            for (int i=0;i<TM;i++)
                #pragma unroll
                for (int j=0;j<TN;j++) acc[i][j] = fmaf(a[i], bb[j], acc[i][j]);
        }
        __syncthreads();
    }

    #pragma unroll
    for (int i=0;i<TM;i++){
        int m = m0 + ty*TM + i;
        float bs = bias[m];
        float4 ov;
        #pragma unroll
        for (int j4 = 0; j4 < TN; j4 += 4) {
            ov.x = acc[i][j4+0] + bs;
            ov.y = acc[i][j4+1] + bs;
            ov.z = acc[i][j4+2] + bs;
            ov.w = acc[i][j4+3] + bs;
            *(float4*)(&Y[((size_t)b*M + m)*N + n0 + tx*TN + j4]) = ov;
        }
    }
}

// ---------------- wd3 transpose: (O,C,3,3) -> [c][kk][o] ------------------------------
__global__ void wd3_transpose_kernel(const float* __restrict__ wd3)
{
    int idx = blockIdx.x*256 + threadIdx.x;
    if (idx < CH*CH*9) {
        int kk = idx % 9;
        int c  = (idx/9) % CH;
        int o  = idx / (9*CH);
        g_wd3t[((size_t)c*9 + kk)*CH + o] = wd3[idx];
    }
}

// ---------------- conv3x3 (SAME) ------------------------------------------------------
// y[b][o][row][px] = bias[o] + sum_{c,dy,dx} w[o][c][dy][dx] * x[b][c][row+dy-1][px+dx-1]
__global__ __launch_bounds__(256)
void conv3x3_kernel(const float* __restrict__ x, const float* __restrict__ bias,
                    float* __restrict__ y)
{
    __shared__ float sx[8*3*66];     // [c][r][xx], xx = col+1 (zero-padded halo)
    __shared__ float sw[8*9*64];     // [c][kk][o]
    const int tid  = threadIdx.x;
    const int yrow = blockIdx.x;
    const int o0   = blockIdx.y*64;
    const int b    = blockIdx.z;
    const int txp  = tid & 15;       // pixel group (4 px each)
    const int tyo  = tid >> 4;       // out-channel group (4 oc each)

    float acc[4][4];
    #pragma unroll
    for (int i=0;i<4;i++)
        #pragma unroll
        for (int j=0;j<4;j++) acc[i][j]=0.f;

    for (int c0 = 0; c0 < CH; c0 += 8) {
        for (int idx = tid; idx < 1584; idx += 256) {
            int c = idx/198, rem = idx%198, r = rem/66, xx = rem%66;
            int yy = yrow + r - 1, col = xx - 1;
            float v = 0.f;
            if (yy >= 0 && yy < HWD && col >= 0 && col < HWD)
                v = x[(((size_t)b*CH + c0 + c)*HWD + yy)*HWD + col];
            sx[idx] = v;
        }
        for (int idx = tid; idx < 4608; idx += 256) {
            int c = idx/576, rem = idx%576, kk = rem/64, o = rem%64;
            sw[idx] = g_wd3t[((size_t)(c0+c)*9 + kk)*CH + o0 + o];
        }
        __syncthreads();
        #pragma unroll
        for (int c=0;c<8;c++){
            #pragma unroll
            for (int dy=0;dy<3;dy++){
                float xv[6];
                #pragma unroll
                for (int q=0;q<6;q++) xv[q] = sx[(c*3+dy)*66 + txp*4 + q];
                #pragma unroll
                for (int dx=0;dx<3;dx++){
                    float wv[4];
                    #pragma unroll
                    for (int i=0;i<4;i++) wv[i] = sw[c*576 + (dy*3+dx)*64 + tyo*4 + i];
                    #pragma unroll
                    for (int i=0;i<4;i++)
                        #pragma unroll
                        for (int j=0;j<4;j++)
                            acc[i][j] = fmaf(wv[i], xv[j+dx], acc[i][j]);
                }
            }
        }
        __syncthreads();
    }

    #pragma unroll
    for (int i=0;i<4;i++){
        int o = o0 + tyo*4 + i;
        float bs = bias[o];
        float4 ov;
        ov.x = acc[i][0]+bs; ov.y = acc[i][1]+bs; ov.z = acc[i][2]+bs; ov.w = acc[i][3]+bs;
        *(float4*)(&y[(((size_t)b*CH + o)*HWD + yrow)*HWD + txp*4]) = ov;
    }
}

// ---------------- energy + softmax -> attn scratch ------------------------------------
// which==0: softmax_j(q1^T k2) -> attn1 ; which==1: softmax_j(q2^T k1) -> attn2
__global__ __launch_bounds__(256)
void energy_softmax_kernel()
{
    extern __shared__ float sh[];
    float* sbuf = sh;                  // 8*4096
    float* kt   = sh + 8*4096;         // 32*256
    float* sq   = kt + 32*256;         // 8*32
    float* sred = sq + 256;            // 8 warps * 8 rows
    float* srow = sred + 64;           // [0..7] max, [8..15] 1/sum

    const int tid = threadIdx.x;
    const int b = blockIdx.z, which = blockIdx.y;
    const int i0 = blockIdx.x * 8;
    const float* q = (which==0 ? g_q1 : g_q2) + (size_t)b*CKD*NPIX;
    const float* k = (which==0 ? g_k2 : g_k1) + (size_t)b*CKD*NPIX;
    float* attn = (which==0 ? g_attn1 : g_attn2) + (size_t)b*NPIX*NPIX;

    { int i = tid >> 5, d = tid & 31; sq[i*32+d] = q[(size_t)d*NPIX + i0 + i]; }
    __syncthreads();

    float rmax[8];
    #pragma unroll
    for (int i=0;i<8;i++) rmax[i] = -1e30f;

    // pass 1: energy, track max
    for (int j0 = 0; j0 < NPIX; j0 += 256) {
        #pragma unroll
        for (int d=0; d<32; d++) kt[d*256+tid] = k[(size_t)d*NPIX + j0 + tid];
        __syncthreads();
        float acc[8];
        #pragma unroll
        for (int i=0;i<8;i++) acc[i] = 0.f;
        #pragma unroll
        for (int d=0;d<32;d++){
            float kd = kt[d*256+tid];
            #pragma unroll
            for (int i=0;i<8;i++) acc[i] = fmaf(sq[i*32+d], kd, acc[i]);
        }
        #pragma unroll
        for (int i=0;i<8;i++){
            sbuf[i*NPIX + j0 + tid] = acc[i];
            rmax[i] = fmaxf(rmax[i], acc[i]);
        }
        __syncthreads();
    }

    const int lane = tid & 31, warp = tid >> 5;
    #pragma unroll
    for (int off=16; off>0; off>>=1)
        #pragma unroll
        for (int i=0;i<8;i++)
            rmax[i] = fmaxf(rmax[i], __shfl_xor_sync(0xffffffffu, rmax[i], off));
    if (lane == 0)
        #pragma unroll
        for (int i=0;i<8;i++) sred[warp*8+i] = rmax[i];
    __syncthreads();
    if (tid < 8) {
        float m = sred[tid];
        #pragma unroll
        for (int w=1;w<8;w++) m = fmaxf(m, sred[w*8+tid]);
        srow[tid] = m;
    }
    __syncthreads();

    float rowmax[8];
    #pragma unroll
    for (int i=0;i<8;i++) rowmax[i] = srow[i];

    // pass 2: exp + sum
    float rsum[8];
    #pragma unroll
    for (int i=0;i<8;i++) rsum[i] = 0.f;
    for (int j0 = 0; j0 < NPIX; j0 += 256) {
        #pragma unroll
        for (int i=0;i<8;i++){
            float p = fast_exp(sbuf[i*NPIX + j0 + tid] - rowmax[i]);
            sbuf[i*NPIX + j0 + tid] = p;
            rsum[i] += p;
        }
    }
    #pragma unroll
    for (int off=16; off>0; off>>=1)
        #pragma unroll
        for (int i=0;i<8;i++)
            rsum[i] += __shfl_xor_sync(0xffffffffu, rsum[i], off);
    if (lane == 0)
        #pragma unroll
        for (int i=0;i<8;i++) sred[warp*8+i] = rsum[i];
    __syncthreads();
    if (tid < 8) {
        float s = sred[tid];
        #pragma unroll
        for (int w=1;w<8;w++) s += sred[w*8+tid];
        srow[8+tid] = 1.0f / s;
    }
    __syncthreads();

    float inv[8];
    #pragma unroll
    for (int i=0;i<8;i++) inv[i] = srow[8+i];

    // pass 3: normalize + write
    for (int j0 = 0; j0 < NPIX; j0 += 256) {
        #pragma unroll
        for (int i=0;i<8;i++)
            attn[(size_t)(i0+i)*NPIX + j0 + tid] = sbuf[i*NPIX + j0 + tid] * inv[i];
    }
}

// ---------------- PV GEMM + fused epilogue --------------------------------------------
// out = x + gamma * (v @ attn^T + d1 + c3)
__global__ __launch_bounds__(256, 2)
void pv_epilogue_kernel(const float* __restrict__ x1, const float* __restrict__ x2,
                        const float* __restrict__ gamma1, const float* __restrict__ gamma2,
                        float* __restrict__ out)
{
    __shared__ float sA[16][132];
    __shared__ float sB[16][132];
    const int tid = threadIdx.x;
    const int bz = blockIdx.z;
    const int b = bz >> 1, which = bz & 1;

    const float* v    = (which==0 ? g_v2   : g_v1)   + (size_t)b*CH*NPIX;
    const float* attn = (which==0 ? g_attn1: g_attn2)+ (size_t)b*NPIX*NPIX;
    const float* xin  = (which==0 ? x1     : x2)     + (size_t)b*CH*NPIX;
    const float* d1   = (which==0 ? g_d1   : g_d2)   + (size_t)b*CH*NPIX;
    const float* c3   = (which==0 ? g_c31  : g_c32)  + (size_t)b*CH*NPIX;
    const float* gp   = (which==0 ? gamma1 : gamma2);
    float* outp = out + (size_t)which*(BATCH*CH*NPIX) + (size_t)b*CH*NPIX;

    const int c0 = blockIdx.y*128, i0 = blockIdx.x*128;

    float acc[8][8];
    #pragma unroll
    for (int i=0;i<8;i++)
        #pragma unroll
        for (int j=0;j<8;j++) acc[i][j]=0.f;

    const int t4 = (tid & 3)*4;
    const int rl = tid >> 2;
    const int ty = tid >> 4, tx = tid & 15;

    for (int j0 = 0; j0 < NPIX; j0 += 16) {
        #pragma unroll
        for (int r=0;r<2;r++){
            int cc = rl + r*64;
            float4 av = *(const float4*)(v + (size_t)(c0+cc)*NPIX + j0 + t4);
            sA[t4+0][cc]=av.x; sA[t4+1][cc]=av.y; sA[t4+2][cc]=av.z; sA[t4+3][cc]=av.w;
            float4 bv = *(const float4*)(attn + (size_t)(i0+cc)*NPIX + j0 + t4);
            sB[t4+0][cc]=bv.x; sB[t4+1][cc]=bv.y; sB[t4+2][cc]=bv.z; sB[t4+3][cc]=bv.w;
        }
        __syncthreads();
        #pragma unroll
        for (int kk=0;kk<16;kk++){
            float4 a0 = *(const float4*)&sA[kk][ty*8];
            float4 a1 = *(const float4*)&sA[kk][ty*8+4];
            float4 b0 = *(const float4*)&sB[kk][tx*8];
            float4 b1 = *(const float4*)&sB[kk][tx*8+4];
            float ar[8] = {a0.x,a0.y,a0.z,a0.w,a1.x,a1.y,a1.z,a1.w};
            float br[8] = {b0.x,b0.y,b0.z,b0.w,b1.x,b1.y,b1.z,b1.w};
            #pragma unroll
            for (int i=0;i<8;i++)
                #pragma unroll
                for (int j=0;j<8;j++)
                    acc[i][j] = fmaf(ar[i], br[j], acc[i][j]);
        }
        __syncthreads();
    }

    const float gamma = gp[0];
    #pragma unroll
    for (int i=0;i<8;i++){
        int cc = c0 + ty*8 + i;
        size_t base = (size_t)cc*NPIX + i0 + tx*8;
        #pragma unroll
        for (int q=0;q<2;q++){
            float4 xv = *(const float4*)(xin + base + q*4);
            float4 dv = *(const float4*)(d1  + base + q*4);
            float4 cv = *(const float4*)(c3  + base + q*4);
            float4 ov;
            ov.x = xv.x + gamma*(acc[i][q*4+0] + dv.x + cv.x);
            ov.y = xv.y + gamma*(acc[i][q*4+1] + dv.y + cv.y);
            ov.z = xv.z + gamma*(acc[i][q*4+2] + dv.z + cv.z);
            ov.w = xv.w + gamma*(acc[i][q*4+3] + dv.w + cv.w);
            *(float4*)(outp + base + q*4) = ov;
        }
    }
}

// ---------------- launch --------------------------------------------------------------
extern "C" void kernel_launch(void* const* d_in, const int* in_sizes, int n_in,
                              void* d_out, int out_size)
{
    const float* x1  = (const float*)d_in[0];
    const float* x2  = (const float*)d_in[1];
    const float* wq1 = (const float*)d_in[2];
    const float* bq1 = (const float*)d_in[3];
    const float* wk1 = (const float*)d_in[4];
    const float* bk1 = (const float*)d_in[5];
    const float* wv1 = (const float*)d_in[6];
    const float* bv1 = (const float*)d_in[7];
    const float* wq2 = (const float*)d_in[8];
    const float* bq2 = (const float*)d_in[9];
    const float* wk2 = (const float*)d_in[10];
    const float* bk2 = (const float*)d_in[11];
    const float* wv2 = (const float*)d_in[12];
    const float* bv2 = (const float*)d_in[13];
    const float* wd1 = (const float*)d_in[14];
    const float* bd1 = (const float*)d_in[15];
    const float* wd3 = (const float*)d_in[16];
    const float* bd3 = (const float*)d_in[17];
    const float* g1  = (const float*)d_in[18];
    const float* g2  = (const float*)d_in[19];
    float* out = (float*)d_out;

    float *p_q1, *p_k1, *p_q2, *p_k2, *p_v1, *p_v2, *p_d1, *p_d2, *p_c31, *p_c32;
    cudaGetSymbolAddress((void**)&p_q1, g_q1);
    cudaGetSymbolAddress((void**)&p_k1, g_k1);
    cudaGetSymbolAddress((void**)&p_q2, g_q2);
    cudaGetSymbolAddress((void**)&p_k2, g_k2);
    cudaGetSymbolAddress((void**)&p_v1, g_v1);
    cudaGetSymbolAddress((void**)&p_v2, g_v2);
    cudaGetSymbolAddress((void**)&p_d1, g_d1);
    cudaGetSymbolAddress((void**)&p_d2, g_d2);
    cudaGetSymbolAddress((void**)&p_c31, g_c31);
    cudaGetSymbolAddress((void**)&p_c32, g_c32);

    // allow 161 KB dynamic smem for the softmax kernel
    cudaFuncSetAttribute(energy_softmax_kernel,
                         cudaFuncAttributeMaxDynamicSharedMemorySize, 166000);

    // 1) projections (1x1 convs)
    dim3 blk(256);
    proj_gemm<32,64,16,2,4><<<dim3(64,1,4), blk>>>(wq1, bq1, x1, p_q1, CKD, CH, NPIX);
    proj_gemm<32,64,16,2,4><<<dim3(64,1,4), blk>>>(wk1, bk1, x1, p_k1, CKD, CH, NPIX);
    proj_gemm<32,64,16,2,4><<<dim3(64,1,4), blk>>>(wq2, bq2, x2, p_q2, CKD, CH, NPIX);
    proj_gemm<32,64,16,2,4><<<dim3(64,1,4), blk>>>(wk2, bk2, x2, p_k2, CKD, CH, NPIX);
    proj_gemm<128,64,16,8,4><<<dim3(64,2,4), blk>>>(wv1, bv1, x1, p_v1, CH, CH, NPIX);
    proj_gemm<128,64,16,8,4><<<dim3(64,2,4), blk>>>(wv2, bv2, x2, p_v2, CH, CH, NPIX);
    proj_gemm<128,64,16,8,4><<<dim3(64,2,4), blk>>>(wd1, bd1, x1, p_d1, CH, CH, NPIX);
    proj_gemm<128,64,16,8,4><<<dim3(64,2,4), blk>>>(wd1, bd1, x2, p_d2, CH, CH, NPIX);

    // 2) conv3x3 branches
    wd3_transpose_kernel<<<2304, 256>>>(wd3);
    conv3x3_kernel<<<dim3(64,4,4), blk>>>(x1, bd3, p_c31);
    conv3x3_kernel<<<dim3(64,4,4), blk>>>(x2, bd3, p_c32);

    // 3) energy + softmax (both attention maps)
    energy_softmax_kernel<<<dim3(512,2,4), blk, 165184>>>();

    // 4) PV GEMM + fused residual epilogue (both outputs)
    pv_epilogue_kernel<<<dim3(32,2,8), blk>>>(x1, x2, g1, g2, out);
}

// round 7
// speedup vs baseline: 2.7765x; 2.7765x over previous
#include <cuda_runtime.h>
#include <cuda_fp16.h>
#include <cstdint>
#include <cstddef>

#define BATCH 4
#define CH    256
#define CKD   32
#define NPIX  4096
#define HWD   64
#define KC    2304   // 9*256 im2col K

// ---------------- scratch (static __device__ — no allocation allowed) ----------------
__device__ __align__(128) float  g_q1[BATCH*CKD*NPIX];
__device__ __align__(128) float  g_k1[BATCH*CKD*NPIX];
__device__ __align__(128) float  g_q2[BATCH*CKD*NPIX];
__device__ __align__(128) float  g_k2[BATCH*CKD*NPIX];
__device__ __align__(128) __half g_xcolT[(size_t)8*NPIX*KC];      // [which*4+b][i][kc]
__device__ __align__(128) __half g_vh[(size_t)8*CH*NPIX];         // v projections fp16
__device__ __align__(128) float  g_db[(size_t)8*CH*NPIX];         // merged residual branch
__device__ __align__(128) __half g_attnh[(size_t)8*NPIX*NPIX];    // attn fp16
__device__ __align__(128) __half g_wvh[2*CH*CH];                  // wv1|wv2 fp16
__device__ __align__(128) __half g_wmh[CH*KC];                    // merged wd3(+wd1 center) fp16
__device__ float g_bm[CH];                                        // bd1+bd3

// ======================= warp-MMA helpers (compute_103-safe PTX) =======================
__device__ __forceinline__ uint32_t smem_to_u32(const void* p) {
    uint32_t a;
    asm("{ .reg .u64 t; cvta.to.shared.u64 t, %1; cvt.u32.u64 %0, t; }" : "=r"(a) : "l"(p));
    return a;
}
__device__ __forceinline__ void ldm_x4(uint32_t r[4], uint32_t addr) {
    asm volatile("ldmatrix.sync.aligned.m8n8.x4.shared.b16 {%0,%1,%2,%3}, [%4];"
                 : "=r"(r[0]), "=r"(r[1]), "=r"(r[2]), "=r"(r[3]) : "r"(addr));
}
__device__ __forceinline__ void mma16816(float c[4], const uint32_t a[4],
                                         uint32_t b0, uint32_t b1) {
    asm volatile("mma.sync.aligned.m16n8k16.row.col.f32.f16.f16.f32 "
                 "{%0,%1,%2,%3}, {%4,%5,%6,%7}, {%8,%9}, {%0,%1,%2,%3};"
                 : "+f"(c[0]), "+f"(c[1]), "+f"(c[2]), "+f"(c[3])
                 : "r"(a[0]), "r"(a[1]), "r"(a[2]), "r"(a[3]), "r"(b0), "r"(b1));
}
__device__ __forceinline__ void cp16(uint32_t saddr, const void* g) {
    asm volatile("cp.async.cg.shared.global [%0], [%1], 16;" :: "r"(saddr), "l"(g));
}

// ---------------- fast exp (poly exp2) -----------------------------------------------
__device__ __forceinline__ float fast_exp(float x) {
    float t = x * 1.4426950408889634f;
    t = fmaxf(t, -126.0f);
    float n = floorf(t);
    float f = t - n;
    float p = 1.5403530393e-4f;
    p = fmaf(p, f, 1.3333558146e-3f);
    p = fmaf(p, f, 9.6181291076e-3f);
    p = fmaf(p, f, 5.5504108665e-2f);
    p = fmaf(p, f, 2.4022650696e-1f);
    p = fmaf(p, f, 6.9314718056e-1f);
    p = fmaf(p, f, 1.0f);
    float s = __int_as_float(((int)n + 127) << 23);
    return p * s;
}

// ---------------- q/k projection GEMM (SIMT fp32, small M) ---------------------------
template<int BM, int BN, int BK, int TM, int TN>
__global__ __launch_bounds__((BM/TM)*(BN/TN))
void proj_gemm(const float* __restrict__ W, const float* __restrict__ bias,
               const float* __restrict__ X, float* __restrict__ Y,
               int M, int C, int N)
{
    constexpr int NT = (BM/TM)*(BN/TN);
    __shared__ float sW[BK][BM+1];
    __shared__ float sX[BK][BN];
    const int tid = threadIdx.x;
    const int b = blockIdx.z;
    const int m0 = blockIdx.y*BM, n0 = blockIdx.x*BN;
    const float* Xb = X + (size_t)b*C*N;

    float acc[TM][TN];
    #pragma unroll
    for (int i=0;i<TM;i++)
        #pragma unroll
        for (int j=0;j<TN;j++) acc[i][j] = 0.f;
    const int tx = tid % (BN/TN), ty = tid / (BN/TN);
    for (int k0 = 0; k0 < C; k0 += BK) {
        #pragma unroll
        for (int idx = tid; idx < BM*BK; idx += NT) {
            int mm = idx / BK, kk = idx % BK;
            sW[kk][mm] = W[(size_t)(m0+mm)*C + k0 + kk];
        }
        #pragma unroll
        for (int idx = tid; idx < BN*BK; idx += NT) {
            int kk = idx / BN, nn = idx % BN;
            sX[kk][nn] = Xb[(size_t)(k0+kk)*N + n0 + nn];
        }
        __syncthreads();
        #pragma unroll
        for (int kk=0;kk<BK;kk++){
            float a[TM], bb[TN];
            #pragma unroll
            for (int i=0;i<TM;i++) a[i] = sW[kk][ty*TM+i];
            #pragma unroll
            for (int j=0;j<TN;j++) bb[j] = sX[kk][tx*TN+j];
            #pragma unroll
            for (int i=0;i<TM;i++)
                #pragma unroll
                for (int j=0;j<TN;j++) acc[i][j] = fmaf(a[i], bb[j], acc[i][j]);
        }
        __syncthreads();
    }
    #pragma unroll
    for (int i=0;i<TM;i++){
        int m = m0 + ty*TM + i;
        float bs = bias[m];
        float4 ov;
        #pragma unroll
        for (int j4 = 0; j4 < TN; j4 += 4) {
            ov.x = acc[i][j4+0] + bs; ov.y = acc[i][j4+1] + bs;
            ov.z = acc[i][j4+2] + bs; ov.w = acc[i][j4+3] + bs;
            *(float4*)(&Y[((size_t)b*M + m)*N + n0 + tx*TN + j4]) = ov;
        }
    }
}

// ---------------- weight prep ---------------------------------------------------------
__global__ void prep_wv_kernel(const float* __restrict__ wv1, const float* __restrict__ wv2)
{
    int idx = blockIdx.x*256 + threadIdx.x;
    if (idx < 2*CH*CH) {
        int w = idx >> 16, r = idx & 65535;
        g_wvh[idx] = __float2half_rn((w ? wv2 : wv1)[r]);
    }
}
__global__ void prep_merged_kernel(const float* __restrict__ wd1, const float* __restrict__ wd3,
                                   const float* __restrict__ bd1, const float* __restrict__ bd3)
{
    int idx = blockIdx.x*256 + threadIdx.x;
    if (idx < CH*KC) {
        int o = idx / KC, kc = idx % KC, kk = kc >> 8, c = kc & 255;
        float v = wd3[((size_t)o*CH + c)*9 + kk];
        if (kk == 4) v += wd1[(size_t)o*CH + c];
        g_wmh[idx] = __float2half_rn(v);
    }
    if (idx < CH) g_bm[idx] = bd1[idx] + bd3[idx];
}

// ---------------- im2col -> fp16 [i][kc] transposed -----------------------------------
__global__ __launch_bounds__(256)
void im2col_kernel(const float* __restrict__ x1, const float* __restrict__ x2)
{
    __shared__ float sx[32][3*66];   // [c][r*66 + xx], xx = col+1 zero-padded
    const int tid = threadIdx.x;
    const int yrow = blockIdx.x;
    const int c0 = blockIdx.y * 32;
    const int z = blockIdx.z;            // which*4 + b
    const int which = z >> 2, b = z & 3;
    const float* x = (which ? x2 : x1) + (size_t)b*CH*NPIX;

    for (int idx = tid; idx < 32*198; idx += 256) {
        int c = idx / 198, rem = idx % 198, r = rem / 66, xx = rem % 66;
        int yy = yrow + r - 1, col = xx - 1;
        float v = 0.f;
        if (yy >= 0 && yy < HWD && col >= 0 && col < HWD)
            v = x[(size_t)(c0+c)*NPIX + yy*HWD + col];
        sx[c][r*66 + xx] = v;
    }
    __syncthreads();
    __half* outp = g_xcolT + (size_t)z*NPIX*KC;
    for (int idx = tid; idx < 64*9*32; idx += 256) {
        int c = idx & 31, kk = (idx >> 5) % 9, i = idx / 288;
        int dy = kk / 3, dx = kk % 3;
        float v = sx[c][dy*66 + i + dx];
        outp[(size_t)(yrow*HWD + i)*KC + kk*256 + c0 + c] = __float2half_rn(v);
    }
}

// ---------------- energy + softmax -> attn fp16 ---------------------------------------
__global__ __launch_bounds__(256)
void energy_softmax_kernel()
{
    extern __shared__ float sh[];
    float* sbuf = sh;                  // 8*4096
    float* kt   = sh + 8*4096;         // 32*256
    float* sq   = kt + 32*256;         // 8*32
    float* sred = sq + 256;            // 64
    float* srow = sred + 64;           // 16

    const int tid = threadIdx.x;
    const int b = blockIdx.z, which = blockIdx.y;
    const int i0 = blockIdx.x * 8;
    const float* q = (which==0 ? g_q1 : g_q2) + (size_t)b*CKD*NPIX;
    const float* k = (which==0 ? g_k2 : g_k1) + (size_t)b*CKD*NPIX;
    __half* attn = g_attnh + (size_t)(which*BATCH + b)*NPIX*NPIX;

    { int i = tid >> 5, d = tid & 31; sq[i*32+d] = q[(size_t)d*NPIX + i0 + i]; }
    __syncthreads();

    float rmax[8];
    #pragma unroll
    for (int i=0;i<8;i++) rmax[i] = -1e30f;

    for (int j0 = 0; j0 < NPIX; j0 += 256) {
        #pragma unroll
        for (int d=0; d<32; d++) kt[d*256+tid] = k[(size_t)d*NPIX + j0 + tid];
        __syncthreads();
        float acc[8];
        #pragma unroll
        for (int i=0;i<8;i++) acc[i] = 0.f;
        #pragma unroll
        for (int d=0;d<32;d++){
            float kd = kt[d*256+tid];
            #pragma unroll
            for (int i=0;i<8;i++) acc[i] = fmaf(sq[i*32+d], kd, acc[i]);
        }
        #pragma unroll
        for (int i=0;i<8;i++){
            sbuf[i*NPIX + j0 + tid] = acc[i];
            rmax[i] = fmaxf(rmax[i], acc[i]);
        }
        __syncthreads();
    }

    const int lane = tid & 31, warp = tid >> 5;
    #pragma unroll
    for (int off=16; off>0; off>>=1)
        #pragma unroll
        for (int i=0;i<8;i++)
            rmax[i] = fmaxf(rmax[i], __shfl_xor_sync(0xffffffffu, rmax[i], off));
    if (lane == 0)
        #pragma unroll
        for (int i=0;i<8;i++) sred[warp*8+i] = rmax[i];
    __syncthreads();
    if (tid < 8) {
        float m = sred[tid];
        #pragma unroll
        for (int w=1;w<8;w++) m = fmaxf(m, sred[w*8+tid]);
        srow[tid] = m;
    }
    __syncthreads();
    float rowmax[8];
    #pragma unroll
    for (int i=0;i<8;i++) rowmax[i] = srow[i];

    float rsum[8];
    #pragma unroll
    for (int i=0;i<8;i++) rsum[i] = 0.f;
    for (int j0 = 0; j0 < NPIX; j0 += 256) {
        #pragma unroll
        for (int i=0;i<8;i++){
            float p = fast_exp(sbuf[i*NPIX + j0 + tid] - rowmax[i]);
            sbuf[i*NPIX + j0 + tid] = p;
            rsum[i] += p;
        }
    }
    #pragma unroll
    for (int off=16; off>0; off>>=1)
        #pragma unroll
        for (int i=0;i<8;i++)
            rsum[i] += __shfl_xor_sync(0xffffffffu, rsum[i], off);
    if (lane == 0)
        #pragma unroll
        for (int i=0;i<8;i++) sred[warp*8+i] = rsum[i];
    __syncthreads();
    if (tid < 8) {
        float s = sred[tid];
        #pragma unroll
        for (int w=1;w<8;w++) s += sred[w*8+tid];
        srow[8+tid] = 1.0f / s;
    }
    __syncthreads();
    float inv[8];
    #pragma unroll
    for (int i=0;i<8;i++) inv[i] = srow[8+i];

    for (int j0 = 0; j0 < NPIX; j0 += 512) {
        #pragma unroll
        for (int i=0;i<8;i++){
            float2 p = *(const float2*)&sbuf[i*NPIX + j0 + 2*tid];
            __half2 h = __floats2half2_rn(p.x*inv[i], p.y*inv[i]);
            *(__half2*)&attn[(size_t)(i0+i)*NPIX + j0 + 2*tid] = h;
        }
    }
}

// ---------------- warp-MMA f16 GEMM: D[128,128] = A[m][k] * B[n][k+kB0] ---------------
// 8 warps: warp_m = wid%4 (32 rows), warp_n = wid/4 (64 cols). mma m16n8k16.
// smem: 2 stages x (A 128x64 + B 128x64) halves, row stride 144B (8-half pad).
#define BKC 64
#define ROWB 144
#define ATILE_B (128*ROWB)
#define STAGE_B (2*ATILE_B)
#define MMA_SMEM (2*STAGE_B)

// MODE 0: v projection  (out fp16 + bias)
// MODE 1: residual branch (out fp32 + bias)
// MODE 2: PV + final epilogue (out = x + gamma*(pv + db))
template<int MODE>
__global__ __launch_bounds__(256)
void mma_gemm_kernel(const float* __restrict__ x1, const float* __restrict__ x2,
                     const float* __restrict__ bv1, const float* __restrict__ bv2,
                     const float* __restrict__ g1, const float* __restrict__ g2,
                     float* __restrict__ outbuf)
{
    extern __shared__ char smem[];
    uint32_t sb = smem_to_u32(smem);
    const int tid = threadIdx.x, wid = tid >> 5, lane = tid & 31;
    const int warp_m = wid & 3, warp_n = wid >> 2;
    const int z = blockIdx.z, which = z >> 2, b = z & 3;
    const int m0 = blockIdx.y*128, n0 = blockIdx.x*128;

    const __half* A; const __half* B;
    int lda, ldb, kstartB, nch;
    const float* bias = nullptr; float gamma = 0.f;
    float* outf = nullptr; __half* outh = nullptr;
    const float* xin = nullptr; const float* db = nullptr;

    if (MODE == 0) {
        A = g_wvh + (size_t)which*CH*CH; lda = CH;
        B = g_xcolT + (size_t)z*NPIX*KC; ldb = KC;
        kstartB = 1024; nch = 4;            // B: center-tap im2col slice; A: k from 0
        bias = which ? bv2 : bv1;
        outh = g_vh + (size_t)z*CH*NPIX;
    } else if (MODE == 1) {
        A = g_wmh; lda = KC;
        B = g_xcolT + (size_t)z*NPIX*KC; ldb = KC;
        kstartB = 0; nch = KC/BKC;          // 36
        bias = g_bm;
        outf = g_db + (size_t)z*CH*NPIX;
    } else {
        A = g_vh + (size_t)((1-which)*BATCH + b)*CH*NPIX; lda = NPIX;
        B = g_attnh + (size_t)z*NPIX*NPIX; ldb = NPIX;
        kstartB = 0; nch = NPIX/BKC;        // 64
        xin = (which ? x2 : x1) + (size_t)b*CH*NPIX;
        db = g_db + (size_t)z*CH*NPIX;
        gamma = __ldg(which ? g2 : g1);
        outf = outbuf + (size_t)which*(BATCH*CH*NPIX) + (size_t)b*CH*NPIX;
    }

    float acc[2][8][4];
    #pragma unroll
    for (int i=0;i<2;i++)
        #pragma unroll
        for (int j=0;j<8;j++)
            #pragma unroll
            for (int q=0;q<4;q++) acc[i][j][q] = 0.f;

    // stage loader: 8 cp.async of 16B per thread. A uses kA (from 0), B uses kstartB+.
    auto load_stage = [&](int c, int s) {
        uint32_t base = sb + (uint32_t)s*STAGE_B;
        int kA = c*BKC;
        int kB = kstartB + c*BKC;
        #pragma unroll
        for (int q = 0; q < 4; q++) {
            int idx = q*256 + tid;
            int row = idx >> 3, seg = idx & 7;
            cp16(base + (uint32_t)(row*ROWB + seg*16),
                 A + (size_t)(m0+row)*lda + kA + seg*8);
            cp16(base + ATILE_B + (uint32_t)(row*ROWB + seg*16),
                 B + (size_t)(n0+row)*ldb + kB + seg*8);
        }
        asm volatile("cp.async.commit_group;" ::: "memory");
    };

    load_stage(0, 0);
    for (int c = 0; c < nch; c++) {
        if (c+1 < nch) {
            load_stage(c+1, (c+1)&1);
            asm volatile("cp.async.wait_group 1;" ::: "memory");
        } else {
            asm volatile("cp.async.wait_group 0;" ::: "memory");
        }
        __syncthreads();
        uint32_t as = sb + (uint32_t)(c&1)*STAGE_B;
        uint32_t bs = as + ATILE_B;
        #pragma unroll
        for (int ks = 0; ks < BKC/16; ks++) {
            uint32_t af[2][4], bf[4][4];
            #pragma unroll
            for (int mt=0; mt<2; mt++) {
                uint32_t row = warp_m*32 + mt*16 + (lane & 15);
                uint32_t col = ks*16 + ((lane >> 4) << 3);
                ldm_x4(af[mt], as + row*ROWB + col*2);
            }
            #pragma unroll
            for (int np=0; np<4; np++) {
                uint32_t row = warp_n*64 + np*16 + (lane & 7) + ((lane >> 4) << 3);
                uint32_t col = ks*16 + (((lane >> 3) & 1) << 3);
                ldm_x4(bf[np], bs + row*ROWB + col*2);
            }
            #pragma unroll
            for (int mt=0; mt<2; mt++)
                #pragma unroll
                for (int nt=0; nt<8; nt++)
                    mma16816(acc[mt][nt], af[mt], bf[nt>>1][(nt&1)*2], bf[nt>>1][(nt&1)*2+1]);
        }
        __syncthreads();
    }

    // epilogue: fragment layout c0,c1 -> row lane/4; c2,c3 -> row lane/4+8; cols 2*(lane%4)
    #pragma unroll
    for (int mt=0; mt<2; mt++) {
        #pragma unroll
        for (int hf=0; hf<2; hf++) {
            int m = m0 + warp_m*32 + mt*16 + (lane >> 2) + hf*8;
            float bsv = 0.f;
            if (MODE < 2) bsv = __ldg(&bias[m]);
            #pragma unroll
            for (int nt=0; nt<8; nt++) {
                int n = n0 + warp_n*64 + nt*8 + 2*(lane & 3);
                float v0 = acc[mt][nt][hf*2+0], v1 = acc[mt][nt][hf*2+1];
                size_t ga = (size_t)m*NPIX + n;
                if (MODE == 0) {
                    *(__half2*)&outh[ga] = __floats2half2_rn(v0 + bsv, v1 + bsv);
                } else if (MODE == 1) {
                    float2 o; o.x = v0 + bsv; o.y = v1 + bsv;
                    *(float2*)&outf[ga] = o;
                } else {
                    float2 xv = *(const float2*)&xin[ga];
                    float2 dv = *(const float2*)&db[ga];
                    float2 o;
                    o.x = xv.x + gamma*(v0 + dv.x);
                    o.y = xv.y + gamma*(v1 + dv.y);
                    *(float2*)&outf[ga] = o;
                }
            }
        }
    }
}

// ---------------- launch --------------------------------------------------------------
extern "C" void kernel_launch(void* const* d_in, const int* in_sizes, int n_in,
                              void* d_out, int out_size)
{
    const float* x1  = (const float*)d_in[0];
    const float* x2  = (const float*)d_in[1];
    const float* wq1 = (const float*)d_in[2];
    const float* bq1 = (const float*)d_in[3];
    const float* wk1 = (const float*)d_in[4];
    const float* bk1 = (const float*)d_in[5];
    const float* wv1 = (const float*)d_in[6];
    const float* bv1 = (const float*)d_in[7];
    const float* wq2 = (const float*)d_in[8];
    const float* bq2 = (const float*)d_in[9];
    const float* wk2 = (const float*)d_in[10];
    const float* bk2 = (const float*)d_in[11];
    const float* wv2 = (const float*)d_in[12];
    const float* bv2 = (const float*)d_in[13];
    const float* wd1 = (const float*)d_in[14];
    const float* bd1 = (const float*)d_in[15];
    const float* wd3 = (const float*)d_in[16];
    const float* bd3 = (const float*)d_in[17];
    const float* g1  = (const float*)d_in[18];
    const float* g2  = (const float*)d_in[19];
    float* out = (float*)d_out;

    float *p_q1, *p_k1, *p_q2, *p_k2;
    cudaGetSymbolAddress((void**)&p_q1, g_q1);
    cudaGetSymbolAddress((void**)&p_k1, g_k1);
    cudaGetSymbolAddress((void**)&p_q2, g_q2);
    cudaGetSymbolAddress((void**)&p_k2, g_k2);

    cudaFuncSetAttribute(energy_softmax_kernel,
                         cudaFuncAttributeMaxDynamicSharedMemorySize, 166000);
    cudaFuncSetAttribute(mma_gemm_kernel<0>,
                         cudaFuncAttributeMaxDynamicSharedMemorySize, MMA_SMEM);
    cudaFuncSetAttribute(mma_gemm_kernel<1>,
                         cudaFuncAttributeMaxDynamicSharedMemorySize, MMA_SMEM);
    cudaFuncSetAttribute(mma_gemm_kernel<2>,
                         cudaFuncAttributeMaxDynamicSharedMemorySize, MMA_SMEM);

    dim3 blk(256);

    // weight prep + im2col (fp16)
    prep_wv_kernel<<<(2*CH*CH + 255)/256, blk>>>(wv1, wv2);
    prep_merged_kernel<<<(CH*KC + 255)/256, blk>>>(wd1, wd3, bd1, bd3);
    im2col_kernel<<<dim3(64, 8, 8), blk>>>(x1, x2);

    // q/k projections (SIMT fp32)
    proj_gemm<32,64,16,2,4><<<dim3(64,1,4), blk>>>(wq1, bq1, x1, p_q1, CKD, CH, NPIX);
    proj_gemm<32,64,16,2,4><<<dim3(64,1,4), blk>>>(wk1, bk1, x1, p_k1, CKD, CH, NPIX);
    proj_gemm<32,64,16,2,4><<<dim3(64,1,4), blk>>>(wq2, bq2, x2, p_q2, CKD, CH, NPIX);
    proj_gemm<32,64,16,2,4><<<dim3(64,1,4), blk>>>(wk2, bk2, x2, p_k2, CKD, CH, NPIX);

    // v projections (tensor cores, fp16 out)
    mma_gemm_kernel<0><<<dim3(32,2,8), blk, MMA_SMEM>>>(x1, x2, bv1, bv2, g1, g2, out);
    // merged residual branch: conv1x1(wd1) + conv3x3(wd3) in one K=2304 GEMM
    mma_gemm_kernel<1><<<dim3(32,2,8), blk, MMA_SMEM>>>(x1, x2, bv1, bv2, g1, g2, out);

    // energy + softmax (fp32 compute, fp16 attn out)
    energy_softmax_kernel<<<dim3(512,2,4), blk, 165184>>>();

    // PV GEMM + fused final epilogue (tensor cores)
    mma_gemm_kernel<2><<<dim3(32,2,8), blk, MMA_SMEM>>>(x1, x2, bv1, bv2, g1, g2, out);
}

// round 8
// speedup vs baseline: 3.0215x; 1.0882x over previous
#include <cuda_runtime.h>
#include <cuda_fp16.h>
#include <cstdint>
#include <cstddef>

#define BATCH 4
#define CH    256
#define NPIX  4096
#define HWD   64
#define KC    2304   // 9*256 im2col K

// ---------------- scratch (static __device__ — no allocation allowed) ----------------
__device__ __align__(128) __half g_xcolT[(size_t)8*NPIX*KC];      // [which*4+b][i][kc]
__device__ __align__(128) __half g_vh[(size_t)8*CH*NPIX];         // v projections fp16 [z][c][i]
__device__ __align__(128) float  g_db[(size_t)8*CH*NPIX];         // merged residual branch
__device__ __align__(128) __half g_qh[(size_t)8*NPIX*32];         // q fp16 [z][i][d]
__device__ __align__(128) __half g_kh[(size_t)8*NPIX*32];         // k fp16 [z][i][d]
__device__ __align__(128) __half g_wvh[2*CH*CH];                  // wv1|wv2 fp16
__device__ __align__(128) __half g_wmh[CH*KC];                    // merged wd3(+wd1 center) fp16
__device__ float g_bm[CH];                                        // bd1+bd3

// ======================= warp-MMA helpers (compute_103-safe PTX) =======================
__device__ __forceinline__ uint32_t smem_to_u32(const void* p) {
    uint32_t a;
    asm("{ .reg .u64 t; cvta.to.shared.u64 t, %1; cvt.u32.u64 %0, t; }" : "=r"(a) : "l"(p));
    return a;
}
__device__ __forceinline__ void ldm_x4(uint32_t r[4], uint32_t addr) {
    asm volatile("ldmatrix.sync.aligned.m8n8.x4.shared.b16 {%0,%1,%2,%3}, [%4];"
                 : "=r"(r[0]), "=r"(r[1]), "=r"(r[2]), "=r"(r[3]) : "r"(addr));
}
__device__ __forceinline__ void mma16816(float c[4], const uint32_t a[4],
                                         uint32_t b0, uint32_t b1) {
    asm volatile("mma.sync.aligned.m16n8k16.row.col.f32.f16.f16.f32 "
                 "{%0,%1,%2,%3}, {%4,%5,%6,%7}, {%8,%9}, {%0,%1,%2,%3};"
                 : "+f"(c[0]), "+f"(c[1]), "+f"(c[2]), "+f"(c[3])
                 : "r"(a[0]), "r"(a[1]), "r"(a[2]), "r"(a[3]), "r"(b0), "r"(b1));
}
__device__ __forceinline__ void cp16(uint32_t saddr, const void* g) {
    asm volatile("cp.async.cg.shared.global [%0], [%1], 16;" :: "r"(saddr), "l"(g));
}
#define CP_COMMIT() asm volatile("cp.async.commit_group;" ::: "memory")
#define CP_WAIT(n)  asm volatile("cp.async.wait_group %0;" :: "n"(n) : "memory")

// ---------------- fast exp (poly exp2) -----------------------------------------------
__device__ __forceinline__ float fast_exp(float x) {
    float t = x * 1.4426950408889634f;
    t = fmaxf(t, -126.0f);
    float n = floorf(t);
    float f = t - n;
    float p = 1.5403530393e-4f;
    p = fmaf(p, f, 1.3333558146e-3f);
    p = fmaf(p, f, 9.6181291076e-3f);
    p = fmaf(p, f, 5.5504108665e-2f);
    p = fmaf(p, f, 2.4022650696e-1f);
    p = fmaf(p, f, 6.9314718056e-1f);
    p = fmaf(p, f, 1.0f);
    float s = __int_as_float(((int)n + 127) << 23);
    return p * s;
}

// ---------------- fused q+k projection -> fp16 [i][d] ---------------------------------
__global__ __launch_bounds__(256)
void qk_proj_kernel(const float* __restrict__ x1, const float* __restrict__ x2,
                    const float* __restrict__ wq1, const float* __restrict__ bq1,
                    const float* __restrict__ wk1, const float* __restrict__ bk1,
                    const float* __restrict__ wq2, const float* __restrict__ bq2,
                    const float* __restrict__ wk2, const float* __restrict__ bk2)
{
    __shared__ float xs[64*64];
    __shared__ float ws[64*65];
    const int tid = threadIdx.x;
    const int z = blockIdx.y, which = z >> 2, b = z & 3;
    const int i0 = blockIdx.x * 64;
    const float* x  = (which ? x2 : x1) + (size_t)b*CH*NPIX;
    const float* wq = which ? wq2 : wq1;
    const float* wk = which ? wk2 : wk1;
    const float* bq = which ? bq2 : bq1;
    const float* bk = which ? bk2 : bk1;
    const int tx = tid & 15, ty = tid >> 4;

    float acc[4][4];
    #pragma unroll
    for (int i=0;i<4;i++)
        #pragma unroll
        for (int j=0;j<4;j++) acc[i][j] = 0.f;

    for (int c0 = 0; c0 < CH; c0 += 64) {
        #pragma unroll
        for (int e=0;e<4;e++){
            int idx = e*256 + tid, cc = idx >> 4, i4 = (idx & 15)*4;
            *(float4*)&xs[cc*64 + i4] = *(const float4*)&x[(size_t)(c0+cc)*NPIX + i0 + i4];
        }
        #pragma unroll
        for (int e=0;e<16;e++){
            int idx = e*256 + tid, o = idx >> 6, cc = idx & 63;
            const float* wsrc = (o < 32) ? (wq + (size_t)o*CH) : (wk + (size_t)(o-32)*CH);
            ws[cc*65 + o] = wsrc[c0+cc];
        }
        __syncthreads();
        #pragma unroll 4
        for (int cc=0; cc<64; cc++){
            float4 xr = *(float4*)&xs[cc*64 + tx*4];
            float xv[4] = {xr.x, xr.y, xr.z, xr.w};
            float wv[4];
            #pragma unroll
            for (int oo=0;oo<4;oo++) wv[oo] = ws[cc*65 + ty*4 + oo];
            #pragma unroll
            for (int oo=0;oo<4;oo++)
                #pragma unroll
                for (int ii=0;ii<4;ii++)
                    acc[oo][ii] = fmaf(wv[oo], xv[ii], acc[oo][ii]);
        }
        __syncthreads();
    }
    #pragma unroll
    for (int oo=0;oo<4;oo++){
        int o = ty*4 + oo;
        float bsv = (o < 32) ? __ldg(&bq[o]) : __ldg(&bk[o-32]);
        __half* dst = (o < 32) ? (g_qh + (size_t)z*NPIX*32) : (g_kh + (size_t)z*NPIX*32);
        int od = (o < 32) ? o : (o - 32);
        #pragma unroll
        for (int ii=0;ii<4;ii++){
            int i = i0 + tx*4 + ii;
            dst[(size_t)i*32 + od] = __float2half_rn(acc[oo][ii] + bsv);
        }
    }
}

// ---------------- weight prep ---------------------------------------------------------
__global__ void prep_wv_kernel(const float* __restrict__ wv1, const float* __restrict__ wv2)
{
    int idx = blockIdx.x*256 + threadIdx.x;
    if (idx < 2*CH*CH) {
        int w = idx >> 16, r = idx & 65535;
        g_wvh[idx] = __float2half_rn((w ? wv2 : wv1)[r]);
    }
}
__global__ void prep_merged_kernel(const float* __restrict__ wd1, const float* __restrict__ wd3,
                                   const float* __restrict__ bd1, const float* __restrict__ bd3)
{
    int idx = blockIdx.x*256 + threadIdx.x;
    if (idx < CH*KC) {
        int o = idx / KC, kc = idx % KC, kk = kc >> 8, c = kc & 255;
        float v = wd3[((size_t)o*CH + c)*9 + kk];
        if (kk == 4) v += wd1[(size_t)o*CH + c];
        g_wmh[idx] = __float2half_rn(v);
    }
    if (idx < CH) g_bm[idx] = bd1[idx] + bd3[idx];
}

// ---------------- im2col -> fp16 [i][kc] transposed -----------------------------------
__global__ __launch_bounds__(256)
void im2col_kernel(const float* __restrict__ x1, const float* __restrict__ x2)
{
    __shared__ float sx[32][3*66];
    const int tid = threadIdx.x;
    const int yrow = blockIdx.x;
    const int c0 = blockIdx.y * 32;
    const int z = blockIdx.z;
    const int which = z >> 2, b = z & 3;
    const float* x = (which ? x2 : x1) + (size_t)b*CH*NPIX;

    for (int idx = tid; idx < 32*198; idx += 256) {
        int c = idx / 198, rem = idx % 198, r = rem / 66, xx = rem % 66;
        int yy = yrow + r - 1, col = xx - 1;
        float v = 0.f;
        if (yy >= 0 && yy < HWD && col >= 0 && col < HWD)
            v = x[(size_t)(c0+c)*NPIX + yy*HWD + col];
        sx[c][r*66 + xx] = v;
    }
    __syncthreads();
    __half* outp = g_xcolT + (size_t)z*NPIX*KC;
    for (int idx = tid; idx < 64*9*32; idx += 256) {
        int c = idx & 31, kk = (idx >> 5) % 9, i = idx / 288;
        int dy = kk / 3, dx = kk % 3;
        float v = sx[c][dy*66 + i + dx];
        outp[(size_t)(yrow*HWD + i)*KC + kk*256 + c0 + c] = __float2half_rn(v);
    }
}

// ---------------- warp-MMA f16 GEMM (v proj / residual branch) ------------------------
#define BKC 64
#define ROWB 144
#define ATILE_B (128*ROWB)
#define STAGE_B (2*ATILE_B)
#define MMA_SMEM (2*STAGE_B)

// MODE 0: v projection (out fp16 + bias, layout [c][i]) ; MODE 1: residual (fp32 + bias)
template<int MODE>
__global__ __launch_bounds__(256)
void mma_gemm_kernel(const float* __restrict__ bv1, const float* __restrict__ bv2)
{
    extern __shared__ char smem[];
    uint32_t sb = smem_to_u32(smem);
    const int tid = threadIdx.x, wid = tid >> 5, lane = tid & 31;
    const int warp_m = wid & 3, warp_n = wid >> 2;
    const int z = blockIdx.z, which = z >> 2;
    const int m0 = blockIdx.y*128, n0 = blockIdx.x*128;

    const __half* A; const __half* B;
    int lda, ldb, kstartB, nch;
    const float* bias; float* outf = nullptr; __half* outh = nullptr;

    if (MODE == 0) {
        A = g_wvh + (size_t)which*CH*CH; lda = CH;
        B = g_xcolT + (size_t)z*NPIX*KC; ldb = KC;
        kstartB = 1024; nch = 4;
        bias = which ? bv2 : bv1;
        outh = g_vh + (size_t)z*CH*NPIX;
    } else {
        A = g_wmh; lda = KC;
        B = g_xcolT + (size_t)z*NPIX*KC; ldb = KC;
        kstartB = 0; nch = KC/BKC;
        bias = g_bm;
        outf = g_db + (size_t)z*CH*NPIX;
    }

    float acc[2][8][4];
    #pragma unroll
    for (int i=0;i<2;i++)
        #pragma unroll
        for (int j=0;j<8;j++)
            #pragma unroll
            for (int q=0;q<4;q++) acc[i][j][q]=0.f;

    auto load_stage = [&](int c, int s) {
        uint32_t base = sb + (uint32_t)s*STAGE_B;
        int kA = c*BKC, kB = kstartB + c*BKC;
        #pragma unroll
        for (int q = 0; q < 4; q++) {
            int idx = q*256 + tid;
            int row = idx >> 3, seg = idx & 7;
            cp16(base + (uint32_t)(row*ROWB + seg*16), A + (size_t)(m0+row)*lda + kA + seg*8);
            cp16(base + ATILE_B + (uint32_t)(row*ROWB + seg*16), B + (size_t)(n0+row)*ldb + kB + seg*8);
        }
        CP_COMMIT();
    };

    load_stage(0, 0);
    for (int c = 0; c < nch; c++) {
        if (c+1 < nch) { load_stage(c+1, (c+1)&1); CP_WAIT(1); }
        else           { CP_WAIT(0); }
        __syncthreads();
        uint32_t as = sb + (uint32_t)(c&1)*STAGE_B;
        uint32_t bs = as + ATILE_B;
        #pragma unroll
        for (int ks = 0; ks < BKC/16; ks++) {
            uint32_t af[2][4], bf[4][4];
            #pragma unroll
            for (int mt=0; mt<2; mt++)
                ldm_x4(af[mt], as + (warp_m*32 + mt*16 + (lane & 15))*ROWB
                               + (ks*16 + ((lane >> 4) << 3))*2);
            #pragma unroll
            for (int np=0; np<4; np++)
                ldm_x4(bf[np], bs + (warp_n*64 + np*16 + (lane & 7) + ((lane >> 4) << 3))*ROWB
                               + (ks*16 + (((lane >> 3) & 1) << 3))*2);
            #pragma unroll
            for (int mt=0; mt<2; mt++)
                #pragma unroll
                for (int nt=0; nt<8; nt++)
                    mma16816(acc[mt][nt], af[mt], bf[nt>>1][(nt&1)*2], bf[nt>>1][(nt&1)*2+1]);
        }
        __syncthreads();
    }

    #pragma unroll
    for (int mt=0; mt<2; mt++) {
        #pragma unroll
        for (int hf=0; hf<2; hf++) {
            int m = m0 + warp_m*32 + mt*16 + (lane >> 2) + hf*8;
            float bsv = __ldg(&bias[m]);
            #pragma unroll
            for (int nt=0; nt<8; nt++) {
                int n = n0 + warp_n*64 + nt*8 + 2*(lane & 3);
                float v0 = acc[mt][nt][hf*2+0], v1 = acc[mt][nt][hf*2+1];
                size_t ga = (size_t)m*NPIX + n;
                if (MODE == 0) *(__half2*)&outh[ga] = __floats2half2_rn(v0 + bsv, v1 + bsv);
                else { float2 o; o.x = v0 + bsv; o.y = v1 + bsv; *(float2*)&outf[ga] = o; }
            }
        }
    }
}

// ---------------- flash attention: QK^T -> softmax -> PV + epilogue, fused ------------
// grid (32 i-tiles, 2 c-halves, 8 zb). 256 thr. warps: wm=wid&3 (32 i rows), wn=wid>>2.
#define ROWQ 80
#define ROWV 272
#define ROWP 272
#define OFF_Q     0
#define OFF_MOLD  10240
#define OFF_L     10752
#define OFF_SCALE 11264
#define OFF_PMAX  11776
#define OFF_PSUM  12800
#define OFF_P     13824
#define OFF_K     48640
#define OFF_V     69120
#define OFF_EPI   48640
#define FLASH_SMEM 138752

__global__ __launch_bounds__(256)
void flash_kernel(const float* __restrict__ x1, const float* __restrict__ x2,
                  const float* __restrict__ g1, const float* __restrict__ g2,
                  float* __restrict__ outbuf)
{
    extern __shared__ char smem[];
    uint32_t sb = smem_to_u32(smem);
    float* smf = (float*)smem;
    const int tid = threadIdx.x, wid = tid >> 5, lane = tid & 31;
    const int wm = wid & 3, wn = wid >> 2;
    const int ch = blockIdx.y, z = blockIdx.z;
    const int which = z >> 2, b = z & 3;
    const int i0 = blockIdx.x * 128;
    const int zo = (1 - which)*BATCH + b;   // source of k and v

    const __half* qg = g_qh + (size_t)z*NPIX*32;
    const __half* kg = g_kh + (size_t)zo*NPIX*32;
    const __half* vg = g_vh + ((size_t)zo*CH + ch*128)*NPIX;
    const float* xin = (which ? x2 : x1) + (size_t)b*CH*NPIX;
    const float* db  = g_db + (size_t)z*CH*NPIX;
    const float gamma = __ldg(which ? g2 : g1);
    float* outp = outbuf + (size_t)which*(BATCH*CH*NPIX) + (size_t)b*CH*NPIX;

    // init row stats
    for (int r = tid; r < 128; r += 256) {
        smf[(OFF_MOLD>>2) + r] = -1e30f;
        smf[(OFF_L>>2) + r] = 0.f;
    }

    float O[2][8][4];
    #pragma unroll
    for (int mt=0;mt<2;mt++)
        #pragma unroll
        for (int nt=0;nt<8;nt++)
            #pragma unroll
            for (int q=0;q<4;q++) O[mt][nt][q]=0.f;

    // q tile load (group 0 together with tile 0)
    #pragma unroll
    for (int qq=0; qq<2; qq++){
        int idx = qq*256 + tid, row = idx >> 2, seg = idx & 3;
        cp16(sb + OFF_Q + row*ROWQ + seg*16, qg + (size_t)(i0+row)*32 + seg*8);
    }
    auto load_tile = [&](int t, int s){
        int j0 = t*128;
        uint32_t kb = sb + OFF_K + s*10240;
        uint32_t vbb = sb + OFF_V + s*34816;
        #pragma unroll
        for (int qq=0; qq<2; qq++){
            int idx = qq*256 + tid, row = idx >> 2, seg = idx & 3;
            cp16(kb + row*ROWQ + seg*16, kg + (size_t)(j0+row)*32 + seg*8);
        }
        #pragma unroll
        for (int qq=0; qq<8; qq++){
            int idx = qq*256 + tid, row = idx >> 4, seg = idx & 15;
            cp16(vbb + row*ROWV + seg*16, vg + (size_t)row*NPIX + j0 + seg*8);
        }
        CP_COMMIT();
    };
    load_tile(0, 0);

    for (int t = 0; t < 32; t++) {
        int s = t & 1;
        if (t+1 < 32) { load_tile(t+1, s^1); CP_WAIT(1); }
        else          { CP_WAIT(0); }
        __syncthreads();

        uint32_t kbase = sb + OFF_K + s*10240;
        uint32_t vbase = sb + OFF_V + s*34816;

        // ---- S = q @ k^T (128x128) ----
        float S[2][8][4];
        #pragma unroll
        for (int mt=0;mt<2;mt++)
            #pragma unroll
            for (int nt=0;nt<8;nt++)
                #pragma unroll
                for (int q=0;q<4;q++) S[mt][nt][q]=0.f;
        #pragma unroll
        for (int ks=0; ks<2; ks++) {
            uint32_t af[2][4], bf[4][4];
            #pragma unroll
            for (int mt=0; mt<2; mt++)
                ldm_x4(af[mt], sb + OFF_Q + (wm*32 + mt*16 + (lane & 15))*ROWQ
                               + (ks*16 + ((lane >> 4) << 3))*2);
            #pragma unroll
            for (int np=0; np<4; np++)
                ldm_x4(bf[np], kbase + (wn*64 + np*16 + (lane & 7) + ((lane >> 4) << 3))*ROWQ
                               + (ks*16 + (((lane >> 3) & 1) << 3))*2);
            #pragma unroll
            for (int mt=0; mt<2; mt++)
                #pragma unroll
                for (int nt=0; nt<8; nt++)
                    mma16816(S[mt][nt], af[mt], bf[nt>>1][(nt&1)*2], bf[nt>>1][(nt&1)*2+1]);
        }

        // ---- row max (partial per warp, then cross warp-pair) ----
        float pm[2][2];
        #pragma unroll
        for (int mt=0;mt<2;mt++)
            #pragma unroll
            for (int hf=0;hf<2;hf++){
                float m = -1e30f;
                #pragma unroll
                for (int nt=0;nt<8;nt++)
                    m = fmaxf(m, fmaxf(S[mt][nt][hf*2], S[mt][nt][hf*2+1]));
                pm[mt][hf] = m;
            }
        #pragma unroll
        for (int off=1; off<=2; off<<=1)
            #pragma unroll
            for (int mt=0;mt<2;mt++)
                #pragma unroll
                for (int hf=0;hf<2;hf++)
                    pm[mt][hf] = fmaxf(pm[mt][hf], __shfl_xor_sync(0xffffffffu, pm[mt][hf], off));
        if ((lane & 3) == 0) {
            #pragma unroll
            for (int mt=0;mt<2;mt++)
                #pragma unroll
                for (int hf=0;hf<2;hf++){
                    int r = wm*32 + mt*16 + (lane >> 2) + hf*8;
                    smf[(OFF_PMAX>>2) + wn*128 + r] = pm[mt][hf];
                }
        }
        __syncthreads();
        if (tid < 128) {
            float mold = smf[(OFF_MOLD>>2) + tid];
            float mtl = fmaxf(smf[(OFF_PMAX>>2) + tid], smf[(OFF_PMAX>>2) + 128 + tid]);
            float mnew = fmaxf(mold, mtl);
            smf[(OFF_SCALE>>2) + tid] = fast_exp(mold - mnew);
            smf[(OFF_MOLD>>2) + tid] = mnew;
        }
        __syncthreads();

        // ---- P = exp(S - m), write to P smem, partial row sums; rescale O ----
        float mrow[2][2], scv[2][2];
        #pragma unroll
        for (int mt=0;mt<2;mt++)
            #pragma unroll
            for (int hf=0;hf<2;hf++){
                int r = wm*32 + mt*16 + (lane >> 2) + hf*8;
                mrow[mt][hf] = smf[(OFF_MOLD>>2) + r];
                scv[mt][hf]  = smf[(OFF_SCALE>>2) + r];
            }
        float ps[2][2] = {{0.f,0.f},{0.f,0.f}};
        #pragma unroll
        for (int mt=0;mt<2;mt++){
            int r0 = wm*32 + mt*16 + (lane >> 2);
            #pragma unroll
            for (int nt=0;nt<8;nt++){
                int cj = wn*64 + nt*8 + 2*(lane & 3);
                float e0 = fast_exp(S[mt][nt][0] - mrow[mt][0]);
                float e1 = fast_exp(S[mt][nt][1] - mrow[mt][0]);
                float e2 = fast_exp(S[mt][nt][2] - mrow[mt][1]);
                float e3 = fast_exp(S[mt][nt][3] - mrow[mt][1]);
                ps[mt][0] += e0 + e1;
                ps[mt][1] += e2 + e3;
                *(__half2*)(smem + OFF_P + r0*ROWP + cj*2)     = __floats2half2_rn(e0, e1);
                *(__half2*)(smem + OFF_P + (r0+8)*ROWP + cj*2) = __floats2half2_rn(e2, e3);
            }
        }
        #pragma unroll
        for (int off=1; off<=2; off<<=1)
            #pragma unroll
            for (int mt=0;mt<2;mt++)
                #pragma unroll
                for (int hf=0;hf<2;hf++)
                    ps[mt][hf] += __shfl_xor_sync(0xffffffffu, ps[mt][hf], off);
        if ((lane & 3) == 0) {
            #pragma unroll
            for (int mt=0;mt<2;mt++)
                #pragma unroll
                for (int hf=0;hf<2;hf++){
                    int r = wm*32 + mt*16 + (lane >> 2) + hf*8;
                    smf[(OFF_PSUM>>2) + wn*128 + r] = ps[mt][hf];
                }
        }
        // rescale O by scale of its rows (O warp role: same wm -> same rows)
        #pragma unroll
        for (int mt=0;mt<2;mt++)
            #pragma unroll
            for (int nt=0;nt<8;nt++){
                O[mt][nt][0] *= scv[mt][0];
                O[mt][nt][1] *= scv[mt][0];
                O[mt][nt][2] *= scv[mt][1];
                O[mt][nt][3] *= scv[mt][1];
            }
        __syncthreads();
        if (tid < 128) {
            smf[(OFF_L>>2) + tid] = smf[(OFF_L>>2) + tid] * smf[(OFF_SCALE>>2) + tid]
                + smf[(OFF_PSUM>>2) + tid] + smf[(OFF_PSUM>>2) + 128 + tid];
        }

        // ---- O += P @ V^T  (A = P from smem, B = V; warp role: wm x wn(c-group)) ----
        #pragma unroll
        for (int ksj=0; ksj<8; ksj++){
            uint32_t pa[2][4], vb[4][4];
            #pragma unroll
            for (int mt=0; mt<2; mt++)
                ldm_x4(pa[mt], sb + OFF_P + (wm*32 + mt*16 + (lane & 15))*ROWP
                               + (ksj*16 + ((lane >> 4) << 3))*2);
            #pragma unroll
            for (int np=0; np<4; np++)
                ldm_x4(vb[np], vbase + (wn*64 + np*16 + (lane & 7) + ((lane >> 4) << 3))*ROWV
                               + (ksj*16 + (((lane >> 3) & 1) << 3))*2);
            #pragma unroll
            for (int mt=0; mt<2; mt++)
                #pragma unroll
                for (int nt=0; nt<8; nt++)
                    mma16816(O[mt][nt], pa[mt], vb[nt>>1][(nt&1)*2], vb[nt>>1][(nt&1)*2+1]);
        }
        __syncthreads();
    }

    // ---- epilogue: divide by l, transpose to [c][i] in smem, fused residual out ----
    float linv[2][2];
    #pragma unroll
    for (int mt=0;mt<2;mt++)
        #pragma unroll
        for (int hf=0;hf<2;hf++){
            int r = wm*32 + mt*16 + (lane >> 2) + hf*8;
            linv[mt][hf] = 1.0f / smf[(OFF_L>>2) + r];
        }
    #pragma unroll
    for (int mt=0;mt<2;mt++){
        int r0 = wm*32 + mt*16 + (lane >> 2);
        #pragma unroll
        for (int nt=0;nt<8;nt++){
            int c0 = wn*64 + nt*8 + 2*(lane & 3);
            smf[(OFF_EPI>>2) + c0*132 + r0]           = O[mt][nt][0]*linv[mt][0];
            smf[(OFF_EPI>>2) + (c0+1)*132 + r0]       = O[mt][nt][1]*linv[mt][0];
            smf[(OFF_EPI>>2) + c0*132 + r0 + 8]       = O[mt][nt][2]*linv[mt][1];
            smf[(OFF_EPI>>2) + (c0+1)*132 + r0 + 8]   = O[mt][nt][3]*linv[mt][1];
        }
    }
    __syncthreads();
    #pragma unroll
    for (int e=0; e<16; e++){
        int idx = e*256 + tid;
        int cl = idx >> 5, i4 = (idx & 31)*4;
        float4 ov = *(float4*)&smf[(OFF_EPI>>2) + cl*132 + i4];
        int gc = ch*128 + cl;
        size_t ga = (size_t)gc*NPIX + i0 + i4;
        float4 xv = *(const float4*)&xin[ga];
        float4 dv = *(const float4*)&db[ga];
        float4 o;
        o.x = xv.x + gamma*(ov.x + dv.x);
        o.y = xv.y + gamma*(ov.y + dv.y);
        o.z = xv.z + gamma*(ov.z + dv.z);
        o.w = xv.w + gamma*(ov.w + dv.w);
        *(float4*)&outp[ga] = o;
    }
}

// ---------------- launch --------------------------------------------------------------
extern "C" void kernel_launch(void* const* d_in, const int* in_sizes, int n_in,
                              void* d_out, int out_size)
{
    const float* x1  = (const float*)d_in[0];
    const float* x2  = (const float*)d_in[1];
    const float* wq1 = (const float*)d_in[2];
    const float* bq1 = (const float*)d_in[3];
    const float* wk1 = (const float*)d_in[4];
    const float* bk1 = (const float*)d_in[5];
    const float* wv1 = (const float*)d_in[6];
    const float* bv1 = (const float*)d_in[7];
    const float* wq2 = (const float*)d_in[8];
    const float* bq2 = (const float*)d_in[9];
    const float* wk2 = (const float*)d_in[10];
    const float* bk2 = (const float*)d_in[11];
    const float* wv2 = (const float*)d_in[12];
    const float* bv2 = (const float*)d_in[13];
    const float* wd1 = (const float*)d_in[14];
    const float* bd1 = (const float*)d_in[15];
    const float* wd3 = (const float*)d_in[16];
    const float* bd3 = (const float*)d_in[17];
    const float* g1  = (const float*)d_in[18];
    const float* g2  = (const float*)d_in[19];
    float* out = (float*)d_out;

    cudaFuncSetAttribute(mma_gemm_kernel<0>,
                         cudaFuncAttributeMaxDynamicSharedMemorySize, MMA_SMEM);
    cudaFuncSetAttribute(mma_gemm_kernel<1>,
                         cudaFuncAttributeMaxDynamicSharedMemorySize, MMA_SMEM);
    cudaFuncSetAttribute(flash_kernel,
                         cudaFuncAttributeMaxDynamicSharedMemorySize, FLASH_SMEM);

    dim3 blk(256);

    // weight prep + im2col (fp16)
    prep_wv_kernel<<<(2*CH*CH + 255)/256, blk>>>(wv1, wv2);
    prep_merged_kernel<<<(CH*KC + 255)/256, blk>>>(wd1, wd3, bd1, bd3);
    im2col_kernel<<<dim3(64, 8, 8), blk>>>(x1, x2);

    // fused q+k projections -> fp16 [i][d]
    qk_proj_kernel<<<dim3(64, 8), blk>>>(x1, x2, wq1, bq1, wk1, bk1, wq2, bq2, wk2, bk2);

    // v projections (tensor cores, fp16 [c][i])
    mma_gemm_kernel<0><<<dim3(32,2,8), blk, MMA_SMEM>>>(bv1, bv2);
    // merged residual branch: conv1x1(wd1) + conv3x3(wd3), K=2304 GEMM
    mma_gemm_kernel<1><<<dim3(32,2,8), blk, MMA_SMEM>>>(bv1, bv2);

    // fused flash attention + final epilogue
    flash_kernel<<<dim3(32,2,8), blk, FLASH_SMEM>>>(x1, x2, g1, g2, out);
}

// round 10
// speedup vs baseline: 4.6587x; 1.5419x over previous
#include <cuda_runtime.h>
#include <cuda_fp16.h>
#include <cstdint>
#include <cstddef>

#define BATCH 4
#define CH    256
#define NPIX  4096
#define HWD   64
#define KC    2304   // 9*256 im2col K

// ---------------- scratch (static __device__ — no allocation allowed) ----------------
__device__ __align__(128) __half g_xcolT[(size_t)8*NPIX*KC];      // [which*4+b][i][kc]
__device__ __align__(128) __half g_vh[(size_t)8*CH*NPIX];         // v projections fp16 [z][c][i]
__device__ __align__(128) float  g_db[(size_t)8*CH*NPIX];         // merged residual branch
__device__ __align__(128) __half g_qh[(size_t)8*NPIX*32];         // q fp16 [z][i][d]
__device__ __align__(128) __half g_kh[(size_t)8*NPIX*32];         // k fp16 [z][i][d]
__device__ __align__(128) __half g_wvh[2*CH*CH];                  // wv1|wv2 fp16
__device__ __align__(128) __half g_wmh[CH*KC];                    // merged wd3(+wd1 center) fp16
__device__ float g_bm[CH];                                        // bd1+bd3

// ======================= warp-MMA helpers (compute_103-safe PTX) =======================
__device__ __forceinline__ uint32_t smem_to_u32(const void* p) {
    uint32_t a;
    asm("{ .reg .u64 t; cvta.to.shared.u64 t, %1; cvt.u32.u64 %0, t; }" : "=r"(a) : "l"(p));
    return a;
}
__device__ __forceinline__ void ldm_x4(uint32_t r[4], uint32_t addr) {
    asm volatile("ldmatrix.sync.aligned.m8n8.x4.shared.b16 {%0,%1,%2,%3}, [%4];"
                 : "=r"(r[0]), "=r"(r[1]), "=r"(r[2]), "=r"(r[3]) : "r"(addr));
}
__device__ __forceinline__ void mma16816(float c[4], const uint32_t a[4],
                                         uint32_t b0, uint32_t b1) {
    asm volatile("mma.sync.aligned.m16n8k16.row.col.f32.f16.f16.f32 "
                 "{%0,%1,%2,%3}, {%4,%5,%6,%7}, {%8,%9}, {%0,%1,%2,%3};"
                 : "+f"(c[0]), "+f"(c[1]), "+f"(c[2]), "+f"(c[3])
                 : "r"(a[0]), "r"(a[1]), "r"(a[2]), "r"(a[3]), "r"(b0), "r"(b1));
}
__device__ __forceinline__ void cp16(uint32_t saddr, const void* g) {
    asm volatile("cp.async.cg.shared.global [%0], [%1], 16;" :: "r"(saddr), "l"(g));
}
#define CP_COMMIT() asm volatile("cp.async.commit_group;" ::: "memory")
#define CP_WAIT(n)  asm volatile("cp.async.wait_group %0;" :: "n"(n) : "memory")

// ---------------- fast exp (poly exp2) -----------------------------------------------
__device__ __forceinline__ float fast_exp(float x) {
    float t = x * 1.4426950408889634f;
    t = fmaxf(t, -126.0f);
    float n = floorf(t);
    float f = t - n;
    float p = 1.5403530393e-4f;
    p = fmaf(p, f, 1.3333558146e-3f);
    p = fmaf(p, f, 9.6181291076e-3f);
    p = fmaf(p, f, 5.5504108665e-2f);
    p = fmaf(p, f, 2.4022650696e-1f);
    p = fmaf(p, f, 6.9314718056e-1f);
    p = fmaf(p, f, 1.0f);
    float s = __int_as_float(((int)n + 127) << 23);
    return p * s;
}

// ---------------- fused q+k projection -> fp16 [i][d] ---------------------------------
__global__ __launch_bounds__(256)
void qk_proj_kernel(const float* __restrict__ x1, const float* __restrict__ x2,
                    const float* __restrict__ wq1, const float* __restrict__ bq1,
                    const float* __restrict__ wk1, const float* __restrict__ bk1,
                    const float* __restrict__ wq2, const float* __restrict__ bq2,
                    const float* __restrict__ wk2, const float* __restrict__ bk2)
{
    __shared__ float xs[64*64];
    __shared__ float ws[64*65];
    const int tid = threadIdx.x;
    const int z = blockIdx.y, which = z >> 2, b = z & 3;
    const int i0 = blockIdx.x * 64;
    const float* x  = (which ? x2 : x1) + (size_t)b*CH*NPIX;
    const float* wq = which ? wq2 : wq1;
    const float* wk = which ? wk2 : wk1;
    const float* bq = which ? bq2 : bq1;
    const float* bk = which ? bk2 : bk1;
    const int tx = tid & 15, ty = tid >> 4;

    float acc[4][4];
    #pragma unroll
    for (int i=0;i<4;i++)
        #pragma unroll
        for (int j=0;j<4;j++) acc[i][j] = 0.f;

    for (int c0 = 0; c0 < CH; c0 += 64) {
        #pragma unroll
        for (int e=0;e<4;e++){
            int idx = e*256 + tid, cc = idx >> 4, i4 = (idx & 15)*4;
            *(float4*)&xs[cc*64 + i4] = *(const float4*)&x[(size_t)(c0+cc)*NPIX + i0 + i4];
        }
        #pragma unroll
        for (int e=0;e<16;e++){
            int idx = e*256 + tid, o = idx >> 6, cc = idx & 63;
            const float* wsrc = (o < 32) ? (wq + (size_t)o*CH) : (wk + (size_t)(o-32)*CH);
            ws[cc*65 + o] = wsrc[c0+cc];
        }
        __syncthreads();
        #pragma unroll 4
        for (int cc=0; cc<64; cc++){
            float4 xr = *(float4*)&xs[cc*64 + tx*4];
            float xv[4] = {xr.x, xr.y, xr.z, xr.w};
            float wv[4];
            #pragma unroll
            for (int oo=0;oo<4;oo++) wv[oo] = ws[cc*65 + ty*4 + oo];
            #pragma unroll
            for (int oo=0;oo<4;oo++)
                #pragma unroll
                for (int ii=0;ii<4;ii++)
                    acc[oo][ii] = fmaf(wv[oo], xv[ii], acc[oo][ii]);
        }
        __syncthreads();
    }
    #pragma unroll
    for (int oo=0;oo<4;oo++){
        int o = ty*4 + oo;
        float bsv = (o < 32) ? __ldg(&bq[o]) : __ldg(&bk[o-32]);
        __half* dst = (o < 32) ? (g_qh + (size_t)z*NPIX*32) : (g_kh + (size_t)z*NPIX*32);
        int od = (o < 32) ? o : (o - 32);
        #pragma unroll
        for (int ii=0;ii<4;ii++){
            int i = i0 + tx*4 + ii;
            dst[(size_t)i*32 + od] = __float2half_rn(acc[oo][ii] + bsv);
        }
    }
}

// ---------------- weight prep ---------------------------------------------------------
__global__ void prep_wv_kernel(const float* __restrict__ wv1, const float* __restrict__ wv2)
{
    int idx = blockIdx.x*256 + threadIdx.x;
    if (idx < 2*CH*CH) {
        int w = idx >> 16, r = idx & 65535;
        g_wvh[idx] = __float2half_rn((w ? wv2 : wv1)[r]);
    }
}
__global__ void prep_merged_kernel(const float* __restrict__ wd1, const float* __restrict__ wd3,
                                   const float* __restrict__ bd1, const float* __restrict__ bd3)
{
    int idx = blockIdx.x*256 + threadIdx.x;
    if (idx < CH*KC) {
        int o = idx / KC, kc = idx % KC, kk = kc >> 8, c = kc & 255;
        float v = wd3[((size_t)o*CH + c)*9 + kk];
        if (kk == 4) v += wd1[(size_t)o*CH + c];
        g_wmh[idx] = __float2half_rn(v);
    }
    if (idx < CH) g_bm[idx] = bd1[idx] + bd3[idx];
}

// ---------------- im2col -> fp16 [i][kc] transposed -----------------------------------
__global__ __launch_bounds__(256)
void im2col_kernel(const float* __restrict__ x1, const float* __restrict__ x2)
{
    __shared__ float sx[32][3*66];
    const int tid = threadIdx.x;
    const int yrow = blockIdx.x;
    const int c0 = blockIdx.y * 32;
    const int z = blockIdx.z;
    const int which = z >> 2, b = z & 3;
    const float* x = (which ? x2 : x1) + (size_t)b*CH*NPIX;

    for (int idx = tid; idx < 32*198; idx += 256) {
        int c = idx / 198, rem = idx % 198, r = rem / 66, xx = rem % 66;
        int yy = yrow + r - 1, col = xx - 1;
        float v = 0.f;
        if (yy >= 0 && yy < HWD && col >= 0 && col < HWD)
            v = x[(size_t)(c0+c)*NPIX + yy*HWD + col];
        sx[c][r*66 + xx] = v;
    }
    __syncthreads();
    __half* outp = g_xcolT + (size_t)z*NPIX*KC;
    for (int idx = tid; idx < 64*9*32; idx += 256) {
        int c = idx & 31, kk = (idx >> 5) % 9, i = idx / 288;
        int dy = kk / 3, dx = kk % 3;
        float v = sx[c][dy*66 + i + dx];
        outp[(size_t)(yrow*HWD + i)*KC + kk*256 + c0 + c] = __float2half_rn(v);
    }
}

// ---------------- warp-MMA f16 GEMM (v proj / residual branch) ------------------------
#define BKC 64
#define ROWB 144
#define ATILE_B (128*ROWB)
#define STAGE_B (2*ATILE_B)
#define MMA_SMEM (2*STAGE_B)

// MODE 0: v projection (out fp16 + bias, layout [c][i]) ; MODE 1: residual (fp32 + bias)
template<int MODE>
__global__ __launch_bounds__(256)
void mma_gemm_kernel(const float* __restrict__ bv1, const float* __restrict__ bv2)
{
    extern __shared__ char smem[];
    uint32_t sb = smem_to_u32(smem);
    const int tid = threadIdx.x, wid = tid >> 5, lane = tid & 31;
    const int warp_m = wid & 3, warp_n = wid >> 2;
    const int z = blockIdx.z, which = z >> 2;
    const int m0 = blockIdx.y*128, n0 = blockIdx.x*128;

    const __half* A; const __half* B;
    int lda, ldb, kstartB, nch;
    const float* bias; float* outf = nullptr; __half* outh = nullptr;

    if (MODE == 0) {
        A = g_wvh + (size_t)which*CH*CH; lda = CH;
        B = g_xcolT + (size_t)z*NPIX*KC; ldb = KC;
        kstartB = 1024; nch = 4;
        bias = which ? bv2 : bv1;
        outh = g_vh + (size_t)z*CH*NPIX;
    } else {
        A = g_wmh; lda = KC;
        B = g_xcolT + (size_t)z*NPIX*KC; ldb = KC;
        kstartB = 0; nch = KC/BKC;
        bias = g_bm;
        outf = g_db + (size_t)z*CH*NPIX;
    }

    float acc[2][8][4];
    #pragma unroll
    for (int i=0;i<2;i++)
        #pragma unroll
        for (int j=0;j<8;j++)
            #pragma unroll
            for (int q=0;q<4;q++) acc[i][j][q]=0.f;

    auto load_stage = [&](int c, int s) {
        uint32_t base = sb + (uint32_t)s*STAGE_B;
        int kA = c*BKC, kB = kstartB + c*BKC;
        #pragma unroll
        for (int q = 0; q < 4; q++) {
            int idx = q*256 + tid;
            int row = idx >> 3, seg = idx & 7;
            cp16(base + (uint32_t)(row*ROWB + seg*16), A + (size_t)(m0+row)*lda + kA + seg*8);
            cp16(base + ATILE_B + (uint32_t)(row*ROWB + seg*16), B + (size_t)(n0+row)*ldb + kB + seg*8);
        }
        CP_COMMIT();
    };

    load_stage(0, 0);
    for (int c = 0; c < nch; c++) {
        if (c+1 < nch) { load_stage(c+1, (c+1)&1); CP_WAIT(1); }
        else           { CP_WAIT(0); }
        __syncthreads();
        uint32_t as = sb + (uint32_t)(c&1)*STAGE_B;
        uint32_t bs = as + ATILE_B;
        #pragma unroll
        for (int ks = 0; ks < BKC/16; ks++) {
            uint32_t af[2][4], bf[4][4];
            #pragma unroll
            for (int mt=0; mt<2; mt++)
                ldm_x4(af[mt], as + (warp_m*32 + mt*16 + (lane & 15))*ROWB
                               + (ks*16 + ((lane >> 4) << 3))*2);
            #pragma unroll
            for (int np=0; np<4; np++)
                ldm_x4(bf[np], bs + (warp_n*64 + np*16 + (lane & 7) + ((lane >> 4) << 3))*ROWB
                               + (ks*16 + (((lane >> 3) & 1) << 3))*2);
            #pragma unroll
            for (int mt=0; mt<2; mt++)
                #pragma unroll
                for (int nt=0; nt<8; nt++)
                    mma16816(acc[mt][nt], af[mt], bf[nt>>1][(nt&1)*2], bf[nt>>1][(nt&1)*2+1]);
        }
        __syncthreads();
    }

    #pragma unroll
    for (int mt=0; mt<2; mt++) {
        #pragma unroll
        for (int hf=0; hf<2; hf++) {
            int m = m0 + warp_m*32 + mt*16 + (lane >> 2) + hf*8;
            float bsv = __ldg(&bias[m]);
            #pragma unroll
            for (int nt=0; nt<8; nt++) {
                int n = n0 + warp_n*64 + nt*8 + 2*(lane & 3);
                float v0 = acc[mt][nt][hf*2+0], v1 = acc[mt][nt][hf*2+1];
                size_t ga = (size_t)m*NPIX + n;
                if (MODE == 0) *(__half2*)&outh[ga] = __floats2half2_rn(v0 + bsv, v1 + bsv);
                else { float2 o; o.x = v0 + bsv; o.y = v1 + bsv; *(float2*)&outf[ga] = o; }
            }
        }
    }
}

// ---------------- flash attention (FA2 warp layout) + fused epilogue ------------------
// grid (32 i-tiles, 2 c-halves, 8 z). 256 thr, 8 warps; warp w owns rows w*16..w*16+15.
// Softmax fully warp-local; P stays in registers (S accum fragment == A operand quads).
#define ROWQ 80
#define ROWV 272
#define OFF_Q   0
#define OFF_K   10240
#define OFF_V   30720
#define OFF_EPI 10240
#define FLASH_SMEM 100352

__global__ __launch_bounds__(256)
void flash_kernel(const float* __restrict__ x1, const float* __restrict__ x2,
                  const float* __restrict__ g1, const float* __restrict__ g2,
                  float* __restrict__ outbuf)
{
    extern __shared__ char smem[];
    uint32_t sb = smem_to_u32(smem);
    float* smf = (float*)smem;
    const int tid = threadIdx.x, wid = tid >> 5, lane = tid & 31;
    const int ch = blockIdx.y, z = blockIdx.z;
    const int which = z >> 2, b = z & 3;
    const int i0 = blockIdx.x * 128;
    const int zo = (1 - which)*BATCH + b;   // source of k and v

    const __half* qg = g_qh + (size_t)z*NPIX*32;
    const __half* kg = g_kh + (size_t)zo*NPIX*32;
    const __half* vg = g_vh + ((size_t)zo*CH + ch*128)*NPIX;
    const float* xin = (which ? x2 : x1) + (size_t)b*CH*NPIX;
    const float* db  = g_db + (size_t)z*CH*NPIX;
    const float gamma = __ldg(which ? g2 : g1);
    float* outp = outbuf + (size_t)which*(BATCH*CH*NPIX) + (size_t)b*CH*NPIX;

    float O[16][4];
    #pragma unroll
    for (int nt=0;nt<16;nt++)
        #pragma unroll
        for (int q=0;q<4;q++) O[nt][q]=0.f;
    float m0r = -1e30f, m1r = -1e30f, l0r = 0.f, l1r = 0.f;

    // prefetch: Q + tile 0 (one group)
    #pragma unroll
    for (int qq=0; qq<2; qq++){
        int idx = qq*256 + tid, row = idx >> 2, seg = idx & 3;
        cp16(sb + OFF_Q + row*ROWQ + seg*16, qg + (size_t)(i0+row)*32 + seg*8);
    }
    auto load_tile = [&](int t, int s){
        int j0 = t*128;
        uint32_t kb = sb + OFF_K + s*10240;
        uint32_t vbb = sb + OFF_V + s*34816;
        #pragma unroll
        for (int qq=0; qq<2; qq++){
            int idx = qq*256 + tid, row = idx >> 2, seg = idx & 3;
            cp16(kb + row*ROWQ + seg*16, kg + (size_t)(j0+row)*32 + seg*8);
        }
        #pragma unroll
        for (int qq=0; qq<8; qq++){
            int idx = qq*256 + tid, row = idx >> 4, seg = idx & 15;
            cp16(vbb + row*ROWV + seg*16, vg + (size_t)row*NPIX + j0 + seg*8);
        }
        CP_COMMIT();
    };
    load_tile(0, 0);
    CP_COMMIT();   // flush Q group together (Q cp16s were issued before load_tile commit anyway)

    for (int t = 0; t < 32; t++) {
        int s = t & 1;
        CP_WAIT(0);
        __syncthreads();   // stage s ready; all warps past previous compute (s^1 free)
        if (t+1 < 32) load_tile(t+1, s^1);

        uint32_t kbase = sb + OFF_K + s*10240;
        uint32_t vbase = sb + OFF_V + s*34816;

        // ---- S = q @ k^T : warp rows 16, all 128 j ----
        float S[16][4];
        #pragma unroll
        for (int nt=0;nt<16;nt++)
            #pragma unroll
            for (int q=0;q<4;q++) S[nt][q]=0.f;
        #pragma unroll
        for (int ks=0; ks<2; ks++){
            uint32_t af[4];
            ldm_x4(af, sb + OFF_Q + (wid*16 + (lane & 15))*ROWQ
                       + (ks*16 + ((lane >> 4) << 3))*2);
            #pragma unroll
            for (int jt=0; jt<8; jt++){
                uint32_t bf[4];
                ldm_x4(bf, kbase + (jt*16 + (lane & 7) + ((lane >> 4) << 3))*ROWQ
                           + (ks*16 + (((lane >> 3) & 1) << 3))*2);
                mma16816(S[jt*2],   af, bf[0], bf[1]);
                mma16816(S[jt*2+1], af, bf[2], bf[3]);
            }
        }

        // ---- warp-local online softmax (rows lane/4 and lane/4+8) ----
        float mt0 = -1e30f, mt1 = -1e30f;
        #pragma unroll
        for (int nt=0;nt<16;nt++){
            mt0 = fmaxf(mt0, fmaxf(S[nt][0], S[nt][1]));
            mt1 = fmaxf(mt1, fmaxf(S[nt][2], S[nt][3]));
        }
        mt0 = fmaxf(mt0, __shfl_xor_sync(0xffffffffu, mt0, 1));
        mt0 = fmaxf(mt0, __shfl_xor_sync(0xffffffffu, mt0, 2));
        mt1 = fmaxf(mt1, __shfl_xor_sync(0xffffffffu, mt1, 1));
        mt1 = fmaxf(mt1, __shfl_xor_sync(0xffffffffu, mt1, 2));
        float mn0 = fmaxf(m0r, mt0), mn1 = fmaxf(m1r, mt1);
        float sc0 = fast_exp(m0r - mn0), sc1 = fast_exp(m1r - mn1);
        m0r = mn0; m1r = mn1;

        float ls0 = 0.f, ls1 = 0.f;
        uint32_t pa[8][4];
        #pragma unroll
        for (int g=0; g<8; g++){
            float e00 = fast_exp(S[2*g][0]   - mn0);
            float e01 = fast_exp(S[2*g][1]   - mn0);
            float e02 = fast_exp(S[2*g][2]   - mn1);
            float e03 = fast_exp(S[2*g][3]   - mn1);
            float e10 = fast_exp(S[2*g+1][0] - mn0);
            float e11 = fast_exp(S[2*g+1][1] - mn0);
            float e12 = fast_exp(S[2*g+1][2] - mn1);
            float e13 = fast_exp(S[2*g+1][3] - mn1);
            ls0 += e00 + e01 + e10 + e11;
            ls1 += e02 + e03 + e12 + e13;
            __half2 h0 = __floats2half2_rn(e00, e01);
            __half2 h1 = __floats2half2_rn(e02, e03);
            __half2 h2 = __floats2half2_rn(e10, e11);
            __half2 h3 = __floats2half2_rn(e12, e13);
            pa[g][0] = *(uint32_t*)&h0;   // TL quad (rows lane/4,  k lo)
            pa[g][1] = *(uint32_t*)&h1;   // BL quad (rows lane/4+8, k lo)
            pa[g][2] = *(uint32_t*)&h2;   // TR quad (k hi)
            pa[g][3] = *(uint32_t*)&h3;   // BR quad
        }
        ls0 += __shfl_xor_sync(0xffffffffu, ls0, 1);
        ls0 += __shfl_xor_sync(0xffffffffu, ls0, 2);
        ls1 += __shfl_xor_sync(0xffffffffu, ls1, 1);
        ls1 += __shfl_xor_sync(0xffffffffu, ls1, 2);
        l0r = l0r*sc0 + ls0;
        l1r = l1r*sc1 + ls1;

        #pragma unroll
        for (int nt=0;nt<16;nt++){
            O[nt][0] *= sc0; O[nt][1] *= sc0;
            O[nt][2] *= sc1; O[nt][3] *= sc1;
        }

        // ---- O += P @ V^T : A = P (registers), B = V tile from smem ----
        #pragma unroll
        for (int g=0; g<8; g++){
            #pragma unroll
            for (int ct=0; ct<8; ct++){
                uint32_t vb[4];
                ldm_x4(vb, vbase + (ct*16 + (lane & 7) + ((lane >> 4) << 3))*ROWV
                           + (g*16 + (((lane >> 3) & 1) << 3))*2);
                mma16816(O[ct*2],   pa[g], vb[0], vb[1]);
                mma16816(O[ct*2+1], pa[g], vb[2], vb[3]);
            }
        }
    }

    // ---- epilogue: /l, transpose [c][i] via smem, fused residual ----
    __syncthreads();   // all warps done with V stages (EPI overlaps K/V smem)
    float linv0 = 1.0f / l0r, linv1 = 1.0f / l1r;
    int r0 = wid*16 + (lane >> 2);
    #pragma unroll
    for (int nt=0; nt<16; nt++){
        int c0 = nt*8 + 2*(lane & 3);
        smf[(OFF_EPI>>2) + c0*132 + r0]         = O[nt][0]*linv0;
        smf[(OFF_EPI>>2) + (c0+1)*132 + r0]     = O[nt][1]*linv0;
        smf[(OFF_EPI>>2) + c0*132 + r0 + 8]     = O[nt][2]*linv1;
        smf[(OFF_EPI>>2) + (c0+1)*132 + r0 + 8] = O[nt][3]*linv1;
    }
    __syncthreads();
    #pragma unroll
    for (int e=0; e<16; e++){
        int idx = e*256 + tid;
        int cl = idx >> 5, i4 = (idx & 31)*4;
        float4 ov = *(float4*)&smf[(OFF_EPI>>2) + cl*132 + i4];
        int gc = ch*128 + cl;
        size_t ga = (size_t)gc*NPIX + i0 + i4;
        float4 xv = *(const float4*)&xin[ga];
        float4 dv = *(const float4*)&db[ga];
        float4 o;
        o.x = xv.x + gamma*(ov.x + dv.x);
        o.y = xv.y + gamma*(ov.y + dv.y);
        o.z = xv.z + gamma*(ov.z + dv.z);
        o.w = xv.w + gamma*(ov.w + dv.w);
        *(float4*)&outp[ga] = o;
    }
}

// ---------------- launch --------------------------------------------------------------
extern "C" void kernel_launch(void* const* d_in, const int* in_sizes, int n_in,
                              void* d_out, int out_size)
{
    const float* x1  = (const float*)d_in[0];
    const float* x2  = (const float*)d_in[1];
    const float* wq1 = (const float*)d_in[2];
    const float* bq1 = (const float*)d_in[3];
    const float* wk1 = (const float*)d_in[4];
    const float* bk1 = (const float*)d_in[5];
    const float* wv1 = (const float*)d_in[6];
    const float* bv1 = (const float*)d_in[7];
    const float* wq2 = (const float*)d_in[8];
    const float* bq2 = (const float*)d_in[9];
    const float* wk2 = (const float*)d_in[10];
    const float* bk2 = (const float*)d_in[11];
    const float* wv2 = (const float*)d_in[12];
    const float* bv2 = (const float*)d_in[13];
    const float* wd1 = (const float*)d_in[14];
    const float* bd1 = (const float*)d_in[15];
    const float* wd3 = (const float*)d_in[16];
    const float* bd3 = (const float*)d_in[17];
    const float* g1  = (const float*)d_in[18];
    const float* g2  = (const float*)d_in[19];
    float* out = (float*)d_out;

    cudaFuncSetAttribute(mma_gemm_kernel<0>,
                         cudaFuncAttributeMaxDynamicSharedMemorySize, MMA_SMEM);
    cudaFuncSetAttribute(mma_gemm_kernel<1>,
                         cudaFuncAttributeMaxDynamicSharedMemorySize, MMA_SMEM);
    cudaFuncSetAttribute(flash_kernel,
                         cudaFuncAttributeMaxDynamicSharedMemorySize, FLASH_SMEM);

    dim3 blk(256);

    // weight prep + im2col (fp16)
    prep_wv_kernel<<<(2*CH*CH + 255)/256, blk>>>(wv1, wv2);
    prep_merged_kernel<<<(CH*KC + 255)/256, blk>>>(wd1, wd3, bd1, bd3);
    im2col_kernel<<<dim3(64, 8, 8), blk>>>(x1, x2);

    // fused q+k projections -> fp16 [i][d]
    qk_proj_kernel<<<dim3(64, 8), blk>>>(x1, x2, wq1, bq1, wk1, bk1, wq2, bq2, wk2, bk2);

    // v projections (tensor cores, fp16 [c][i])
    mma_gemm_kernel<0><<<dim3(32,2,8), blk, MMA_SMEM>>>(bv1, bv2);
    // merged residual branch: conv1x1(wd1) + conv3x3(wd3), K=2304 GEMM
    mma_gemm_kernel<1><<<dim3(32,2,8), blk, MMA_SMEM>>>(bv1, bv2);

    // fused flash attention (FA2 layout) + final epilogue
    flash_kernel<<<dim3(32,2,8), blk, FLASH_SMEM>>>(x1, x2, g1, g2, out);
}

// round 14
// speedup vs baseline: 6.4483x; 1.3841x over previous
#include <cuda_runtime.h>
#include <cuda_fp16.h>
#include <cstdint>
#include <cstddef>

#define BATCH 4
#define CH    256
#define NPIX  4096
#define HWD   64
#define KC    2304   // 9*256 im2col K

// ---------------- scratch (static __device__ — no allocation allowed) ----------------
__device__ __align__(128) __half g_xcolT[(size_t)8*NPIX*KC];      // [which*4+b][i][kc]
__device__ __align__(128) __half g_vh[(size_t)8*CH*NPIX];         // v projections fp16 [z][c][i]
__device__ __align__(128) float  g_db[(size_t)8*CH*NPIX];         // merged residual branch
__device__ __align__(128) __half g_qh[(size_t)8*NPIX*32];         // q fp16 [z][i][d]
__device__ __align__(128) __half g_kh[(size_t)8*NPIX*32];         // k fp16 [z][i][d]
__device__ __align__(128) __half g_wvh[2*CH*CH];                  // wv1|wv2 fp16
__device__ __align__(128) __half g_wmh[CH*KC];                    // merged wd3(+wd1 center) fp16
__device__ __align__(128) __half g_wqkh[2*64*CH];                 // [which][wq(32);wk(32)][256]
__device__ float g_bm[CH];                                        // bd1+bd3
__device__ float g_bqk[2*64];                                     // [which][bq;bk]

// ======================= warp-MMA helpers (compute_103-safe PTX) =======================
__device__ __forceinline__ uint32_t smem_to_u32(const void* p) {
    uint32_t a;
    asm("{ .reg .u64 t; cvta.to.shared.u64 t, %1; cvt.u32.u64 %0, t; }" : "=r"(a) : "l"(p));
    return a;
}
__device__ __forceinline__ void ldm_x4(uint32_t r[4], uint32_t addr) {
    asm volatile("ldmatrix.sync.aligned.m8n8.x4.shared.b16 {%0,%1,%2,%3}, [%4];"
                 : "=r"(r[0]), "=r"(r[1]), "=r"(r[2]), "=r"(r[3]) : "r"(addr));
}
__device__ __forceinline__ void mma16816(float c[4], const uint32_t a[4],
                                         uint32_t b0, uint32_t b1) {
    asm volatile("mma.sync.aligned.m16n8k16.row.col.f32.f16.f16.f32 "
                 "{%0,%1,%2,%3}, {%4,%5,%6,%7}, {%8,%9}, {%0,%1,%2,%3};"
                 : "+f"(c[0]), "+f"(c[1]), "+f"(c[2]), "+f"(c[3])
                 : "r"(a[0]), "r"(a[1]), "r"(a[2]), "r"(a[3]), "r"(b0), "r"(b1));
}
__device__ __forceinline__ void cp16(uint32_t saddr, const void* g) {
    asm volatile("cp.async.cg.shared.global [%0], [%1], 16;" :: "r"(saddr), "l"(g));
}
#define CP_COMMIT() asm volatile("cp.async.commit_group;" ::: "memory")
#define CP_WAIT(n)  asm volatile("cp.async.wait_group %0;" :: "n"(n) : "memory")

// MUFU exp2 (~2^-22 rel err, 1 instr)
__device__ __forceinline__ float ex2f(float x) {
    float y;
    asm("ex2.approx.ftz.f32 %0, %1;" : "=f"(y) : "f"(x));
    return y;
}
#define L2E 1.4426950408889634f

// ---------------- unified weight prep -------------------------------------------------
__global__ void prep_all_kernel(const float* __restrict__ wv1, const float* __restrict__ wv2,
                                const float* __restrict__ wd1, const float* __restrict__ wd3,
                                const float* __restrict__ bd1, const float* __restrict__ bd3,
                                const float* __restrict__ wq1, const float* __restrict__ wk1,
                                const float* __restrict__ wq2, const float* __restrict__ wk2,
                                const float* __restrict__ bq1, const float* __restrict__ bk1,
                                const float* __restrict__ bq2, const float* __restrict__ bk2)
{
    int idx = blockIdx.x*256 + threadIdx.x;
    if (idx < CH*KC) {
        int o = idx / KC, kc = idx % KC, kk = kc >> 8, c = kc & 255;
        float v = wd3[((size_t)o*CH + c)*9 + kk];
        if (kk == 4) v += wd1[(size_t)o*CH + c];
        g_wmh[idx] = __float2half_rn(v);
    }
    if (idx < 2*CH*CH) {
        int w = idx >> 16, r = idx & 65535;
        g_wvh[idx] = __float2half_rn((w ? wv2 : wv1)[r]);
    }
    if (idx < 2*64*CH) {
        int w = idx / (64*CH), rem = idx % (64*CH), r = rem / CH, c = rem % CH;
        const float* src = (r < 32) ? (w ? wq2 : wq1) : (w ? wk2 : wk1);
        int rr = r & 31;
        g_wqkh[idx] = __float2half_rn(src[(size_t)rr*CH + c]);
    }
    if (idx < CH) g_bm[idx] = bd1[idx] + bd3[idx];
    if (idx < 2*64) {
        int w = idx >> 6, r = idx & 63;
        const float* src = (r < 32) ? (w ? bq2 : bq1) : (w ? bk2 : bk1);
        g_bqk[idx] = src[r & 31];
    }
}

// ---------------- im2col -> fp16 [i][kc] transposed -----------------------------------
__global__ __launch_bounds__(256)
void im2col_kernel(const float* __restrict__ x1, const float* __restrict__ x2)
{
    __shared__ float sx[32][3*66];
    const int tid = threadIdx.x;
    const int yrow = blockIdx.x;
    const int c0 = blockIdx.y * 32;
    const int z = blockIdx.z;
    const int which = z >> 2, b = z & 3;
    const float* x = (which ? x2 : x1) + (size_t)b*CH*NPIX;

    for (int idx = tid; idx < 32*198; idx += 256) {
        int c = idx / 198, rem = idx % 198, r = rem / 66, xx = rem % 66;
        int yy = yrow + r - 1, col = xx - 1;
        float v = 0.f;
        if (yy >= 0 && yy < HWD && col >= 0 && col < HWD)
            v = x[(size_t)(c0+c)*NPIX + yy*HWD + col];
        sx[c][r*66 + xx] = v;
    }
    __syncthreads();
    __half* outp = g_xcolT + (size_t)z*NPIX*KC;
    for (int idx = tid; idx < 64*9*32; idx += 256) {
        int c = idx & 31, kk = (idx >> 5) % 9, i = idx / 288;
        int dy = kk / 3, dx = kk % 3;
        float v = sx[c][dy*66 + i + dx];
        outp[(size_t)(yrow*HWD + i)*KC + kk*256 + c0 + c] = __float2half_rn(v);
    }
}

// ---------------- warp-MMA f16 GEMM (v proj / residual branch), 3-stage ---------------
#define BKC 64
#define ROWB 144
#define ATILE_B (128*ROWB)
#define STAGE_B (2*ATILE_B)
#define MMA_SMEM (3*STAGE_B)

// MODE 0: v projection (out fp16 + bias, layout [c][i]) ; MODE 1: residual (fp32 + bias)
template<int MODE>
__global__ __launch_bounds__(256)
void mma_gemm_kernel(const float* __restrict__ bv1, const float* __restrict__ bv2)
{
    extern __shared__ char smem[];
    uint32_t sb = smem_to_u32(smem);
    const int tid = threadIdx.x, wid = tid >> 5, lane = tid & 31;
    const int warp_m = wid & 3, warp_n = wid >> 2;
    const int z = blockIdx.z, which = z >> 2;
    const int m0 = blockIdx.y*128, n0 = blockIdx.x*128;

    const __half* A; const __half* B;
    int lda, ldb, kstartB, nch;
    const float* bias; float* outf = nullptr; __half* outh = nullptr;

    if (MODE == 0) {
        A = g_wvh + (size_t)which*CH*CH; lda = CH;
        B = g_xcolT + (size_t)z*NPIX*KC; ldb = KC;
        kstartB = 1024; nch = 4;
        bias = which ? bv2 : bv1;
        outh = g_vh + (size_t)z*CH*NPIX;
    } else {
        A = g_wmh; lda = KC;
        B = g_xcolT + (size_t)z*NPIX*KC; ldb = KC;
        kstartB = 0; nch = KC/BKC;
        bias = g_bm;
        outf = g_db + (size_t)z*CH*NPIX;
    }

    float acc[2][8][4];
    #pragma unroll
    for (int i=0;i<2;i++)
        #pragma unroll
        for (int j=0;j<8;j++)
            #pragma unroll
            for (int q=0;q<4;q++) acc[i][j][q]=0.f;

    auto load_stage = [&](int c, int s) {
        uint32_t base = sb + (uint32_t)s*STAGE_B;
        int kA = c*BKC, kB = kstartB + c*BKC;
        #pragma unroll
        for (int q = 0; q < 4; q++) {
            int idx = q*256 + tid;
            int row = idx >> 3, seg = idx & 7;
            cp16(base + (uint32_t)(row*ROWB + seg*16), A + (size_t)(m0+row)*lda + kA + seg*8);
            cp16(base + ATILE_B + (uint32_t)(row*ROWB + seg*16), B + (size_t)(n0+row)*ldb + kB + seg*8);
        }
        CP_COMMIT();
    };

    load_stage(0, 0);
    load_stage(1, 1);
    for (int c = 0; c < nch; c++) {
        if (c+1 < nch) { CP_WAIT(1); } else { CP_WAIT(0); }
        __syncthreads();
        if (c+2 < nch) load_stage(c+2, (c+2)%3);
        uint32_t as = sb + (uint32_t)(c%3)*STAGE_B;
        uint32_t bs = as + ATILE_B;
        #pragma unroll
        for (int ks = 0; ks < BKC/16; ks++) {
            uint32_t af[2][4], bf[4][4];
            #pragma unroll
            for (int mt=0; mt<2; mt++)
                ldm_x4(af[mt], as + (warp_m*32 + mt*16 + (lane & 15))*ROWB
                               + (ks*16 + ((lane >> 4) << 3))*2);
            #pragma unroll
            for (int np=0; np<4; np++)
                ldm_x4(bf[np], bs + (warp_n*64 + np*16 + (lane & 7) + ((lane >> 4) << 3))*ROWB
                               + (ks*16 + (((lane >> 3) & 1) << 3))*2);
            #pragma unroll
            for (int mt=0; mt<2; mt++)
                #pragma unroll
                for (int nt=0; nt<8; nt++)
                    mma16816(acc[mt][nt], af[mt], bf[nt>>1][(nt&1)*2], bf[nt>>1][(nt&1)*2+1]);
        }
    }

    #pragma unroll
    for (int mt=0; mt<2; mt++) {
        #pragma unroll
        for (int hf=0; hf<2; hf++) {
            int m = m0 + warp_m*32 + mt*16 + (lane >> 2) + hf*8;
            float bsv = __ldg(&bias[m]);
            #pragma unroll
            for (int nt=0; nt<8; nt++) {
                int n = n0 + warp_n*64 + nt*8 + 2*(lane & 3);
                float v0 = acc[mt][nt][hf*2+0], v1 = acc[mt][nt][hf*2+1];
                size_t ga = (size_t)m*NPIX + n;
                if (MODE == 0) *(__half2*)&outh[ga] = __floats2half2_rn(v0 + bsv, v1 + bsv);
                else { float2 o; o.x = v0 + bsv; o.y = v1 + bsv; *(float2*)&outf[ga] = o; }
            }
        }
    }
}

// ---------------- q+k projection via HMMA: [64 d-rows] x [4096 i], K=256 --------------
// grid (32, 1, 8). Warps: wm=wid&1 (32 d-rows), wn=wid>>1 (32 i-cols). Out: [i][d] fp16.
#define QK_ATILE (64*ROWB)
#define QK_BTILE (128*ROWB)
#define QK_STAGE (QK_ATILE + QK_BTILE)
#define QK_SMEM  (3*QK_STAGE)

__global__ __launch_bounds__(256)
void qk_mma_kernel()
{
    extern __shared__ char smem[];
    uint32_t sb = smem_to_u32(smem);
    const int tid = threadIdx.x, wid = tid >> 5, lane = tid & 31;
    const int wm = wid & 1, wn = wid >> 1;
    const int z = blockIdx.z, which = z >> 2;
    const int n0 = blockIdx.x*128;

    const __half* A = g_wqkh + (size_t)which*64*CH;
    const __half* B = g_xcolT + (size_t)z*NPIX*KC;

    float acc[2][4][4];
    #pragma unroll
    for (int i=0;i<2;i++)
        #pragma unroll
        for (int j=0;j<4;j++)
            #pragma unroll
            for (int q=0;q<4;q++) acc[i][j][q]=0.f;

    auto load_stage = [&](int c, int s) {
        uint32_t base = sb + (uint32_t)s*QK_STAGE;
        int kA = c*BKC, kB = 1024 + c*BKC;
        #pragma unroll
        for (int q = 0; q < 2; q++) {
            int idx = q*256 + tid, row = idx >> 3, seg = idx & 7;
            cp16(base + (uint32_t)(row*ROWB + seg*16), A + (size_t)row*CH + kA + seg*8);
        }
        #pragma unroll
        for (int q = 0; q < 4; q++) {
            int idx = q*256 + tid, row = idx >> 3, seg = idx & 7;
            cp16(base + QK_ATILE + (uint32_t)(row*ROWB + seg*16),
                 B + (size_t)(n0+row)*KC + kB + seg*8);
        }
        CP_COMMIT();
    };

    load_stage(0, 0);
    load_stage(1, 1);
    for (int c = 0; c < 4; c++) {
        if (c+1 < 4) { CP_WAIT(1); } else { CP_WAIT(0); }
        __syncthreads();
        if (c+2 < 4) load_stage(c+2, (c+2)%3);
        uint32_t as = sb + (uint32_t)(c%3)*QK_STAGE;
        uint32_t bs = as + QK_ATILE;
        #pragma unroll
        for (int ks = 0; ks < 4; ks++) {
            uint32_t af[2][4], bf[2][4];
            #pragma unroll
            for (int mt=0; mt<2; mt++)
                ldm_x4(af[mt], as + (wm*32 + mt*16 + (lane & 15))*ROWB
                               + (ks*16 + ((lane >> 4) << 3))*2);
            #pragma unroll
            for (int np=0; np<2; np++)
                ldm_x4(bf[np], bs + (wn*32 + np*16 + (lane & 7) + ((lane >> 4) << 3))*ROWB
                               + (ks*16 + (((lane >> 3) & 1) << 3))*2);
            #pragma unroll
            for (int mt=0; mt<2; mt++)
                #pragma unroll
                for (int nt=0; nt<4; nt++)
                    mma16816(acc[mt][nt], af[mt], bf[nt>>1][(nt&1)*2], bf[nt>>1][(nt&1)*2+1]);
        }
    }

    __half* qdst = g_qh + (size_t)z*NPIX*32;
    __half* kdst = g_kh + (size_t)z*NPIX*32;
    #pragma unroll
    for (int mt=0; mt<2; mt++) {
        #pragma unroll
        for (int hf=0; hf<2; hf++) {
            int m = wm*32 + mt*16 + (lane >> 2) + hf*8;
            float bsv = __ldg(&g_bqk[which*64 + m]);
            __half* dst = (m < 32) ? qdst : kdst;
            int od = m & 31;
            #pragma unroll
            for (int nt=0; nt<4; nt++) {
                int i = n0 + wn*32 + nt*8 + 2*(lane & 3);
                dst[(size_t)i*32 + od]     = __float2half_rn(acc[mt][nt][hf*2+0] + bsv);
                dst[(size_t)(i+1)*32 + od] = __float2half_rn(acc[mt][nt][hf*2+1] + bsv);
            }
        }
    }
}

// ---------------- flash attention (FA2 warp layout) + fused epilogue ------------------
// grid (32 i-tiles, 2 c-halves, 8 z). 256 thr, 8 warps; warp w owns rows w*16..w*16+15.
#define ROWQ 80
#define ROWV 272
#define OFF_Q   0
#define OFF_K   10240
#define OFF_V   30720
#define OFF_EPI 10240
#define FLASH_SMEM 100352

__global__ __launch_bounds__(256)
void flash_kernel(const float* __restrict__ x1, const float* __restrict__ x2,
                  const float* __restrict__ g1, const float* __restrict__ g2,
                  float* __restrict__ outbuf)
{
    extern __shared__ char smem[];
    uint32_t sb = smem_to_u32(smem);
    float* smf = (float*)smem;
    const int tid = threadIdx.x, wid = tid >> 5, lane = tid & 31;
    const int ch = blockIdx.y, z = blockIdx.z;
    const int which = z >> 2, b = z & 3;
    const int i0 = blockIdx.x * 128;
    const int zo = (1 - which)*BATCH + b;   // source of k and v

    const __half* qg = g_qh + (size_t)z*NPIX*32;
    const __half* kg = g_kh + (size_t)zo*NPIX*32;
    const __half* vg = g_vh + ((size_t)zo*CH + ch*128)*NPIX;
    const float* xin = (which ? x2 : x1) + (size_t)b*CH*NPIX;
    const float* db  = g_db + (size_t)z*CH*NPIX;
    const float gamma = __ldg(which ? g2 : g1);
    float* outp = outbuf + (size_t)which*(BATCH*CH*NPIX) + (size_t)b*CH*NPIX;

    float O[16][4];
    #pragma unroll
    for (int nt=0;nt<16;nt++)
        #pragma unroll
        for (int q=0;q<4;q++) O[nt][q]=0.f;
    float m0r = -1e30f, m1r = -1e30f, l0r = 0.f, l1r = 0.f;

    // prefetch: Q + tile 0 (same group)
    #pragma unroll
    for (int qq=0; qq<2; qq++){
        int idx = qq*256 + tid, row = idx >> 2, seg = idx & 3;
        cp16(sb + OFF_Q + row*ROWQ + seg*16, qg + (size_t)(i0+row)*32 + seg*8);
    }
    auto load_tile = [&](int t, int s){
        int j0 = t*128;
        uint32_t kb = sb + OFF_K + s*10240;
        uint32_t vbb = sb + OFF_V + s*34816;
        #pragma unroll
        for (int qq=0; qq<2; qq++){
            int idx = qq*256 + tid, row = idx >> 2, seg = idx & 3;
            cp16(kb + row*ROWQ + seg*16, kg + (size_t)(j0+row)*32 + seg*8);
        }
        #pragma unroll
        for (int qq=0; qq<8; qq++){
            int idx = qq*256 + tid, row = idx >> 4, seg = idx & 15;
            cp16(vbb + row*ROWV + seg*16, vg + (size_t)row*NPIX + j0 + seg*8);
        }
        CP_COMMIT();
    };
    load_tile(0, 0);

    // wait Q+tile0, hoist loop-invariant Q fragments
    CP_WAIT(0);
    __syncthreads();
    uint32_t qf[2][4];
    #pragma unroll
    for (int ks=0; ks<2; ks++)
        ldm_x4(qf[ks], sb + OFF_Q + (wid*16 + (lane & 15))*ROWQ
                       + (ks*16 + ((lane >> 4) << 3))*2);

    for (int t = 0; t < 32; t++) {
        int s = t & 1;
        if (t > 0) {
            CP_WAIT(0);
            __syncthreads();
        }
        if (t+1 < 32) load_tile(t+1, s^1);

        uint32_t kbase = sb + OFF_K + s*10240;
        uint32_t vbase = sb + OFF_V + s*34816;

        // ---- S = q @ k^T ----
        float S[16][4];
        #pragma unroll
        for (int nt=0;nt<16;nt++)
            #pragma unroll
            for (int q=0;q<4;q++) S[nt][q]=0.f;
        #pragma unroll
        for (int ks=0; ks<2; ks++){
            #pragma unroll
            for (int jt=0; jt<8; jt++){
                uint32_t bf[4];
                ldm_x4(bf, kbase + (jt*16 + (lane & 7) + ((lane >> 4) << 3))*ROWQ
                           + (ks*16 + (((lane >> 3) & 1) << 3))*2);
                mma16816(S[jt*2],   qf[ks], bf[0], bf[1]);
                mma16816(S[jt*2+1], qf[ks], bf[2], bf[3]);
            }
        }

        // ---- warp-local online softmax (MUFU ex2) ----
        float mt0 = -1e30f, mt1 = -1e30f;
        #pragma unroll
        for (int nt=0;nt<16;nt++){
            mt0 = fmaxf(mt0, fmaxf(S[nt][0], S[nt][1]));
            mt1 = fmaxf(mt1, fmaxf(S[nt][2], S[nt][3]));
        }
        mt0 = fmaxf(mt0, __shfl_xor_sync(0xffffffffu, mt0, 1));
        mt0 = fmaxf(mt0, __shfl_xor_sync(0xffffffffu, mt0, 2));
        mt1 = fmaxf(mt1, __shfl_xor_sync(0xffffffffu, mt1, 1));
        mt1 = fmaxf(mt1, __shfl_xor_sync(0xffffffffu, mt1, 2));
        float mn0 = fmaxf(m0r, mt0), mn1 = fmaxf(m1r, mt1);
        float sc0 = ex2f((m0r - mn0)*L2E), sc1 = ex2f((m1r - mn1)*L2E);
        m0r = mn0; m1r = mn1;
        float mnl0 = mn0*L2E, mnl1 = mn1*L2E;

        float ls0 = 0.f, ls1 = 0.f;
        uint32_t pa[8][4];
        #pragma unroll
        for (int g=0; g<8; g++){
            float e00 = ex2f(fmaf(S[2*g][0],   L2E, -mnl0));
            float e01 = ex2f(fmaf(S[2*g][1],   L2E, -mnl0));
            float e02 = ex2f(fmaf(S[2*g][2],   L2E, -mnl1));
            float e03 = ex2f(fmaf(S[2*g][3],   L2E, -mnl1));
            float e10 = ex2f(fmaf(S[2*g+1][0], L2E, -mnl0));
            float e11 = ex2f(fmaf(S[2*g+1][1], L2E, -mnl0));
            float e12 = ex2f(fmaf(S[2*g+1][2], L2E, -mnl1));
            float e13 = ex2f(fmaf(S[2*g+1][3], L2E, -mnl1));
            ls0 += e00 + e01 + e10 + e11;
            ls1 += e02 + e03 + e12 + e13;
            __half2 h0 = __floats2half2_rn(e00, e01);
            __half2 h1 = __floats2half2_rn(e02, e03);
            __half2 h2 = __floats2half2_rn(e10, e11);
            __half2 h3 = __floats2half2_rn(e12, e13);
            pa[g][0] = *(uint32_t*)&h0;
            pa[g][1] = *(uint32_t*)&h1;
            pa[g][2] = *(uint32_t*)&h2;
            pa[g][3] = *(uint32_t*)&h3;
        }
        ls0 += __shfl_xor_sync(0xffffffffu, ls0, 1);
        ls0 += __shfl_xor_sync(0xffffffffu, ls0, 2);
        ls1 += __shfl_xor_sync(0xffffffffu, ls1, 1);
        ls1 += __shfl_xor_sync(0xffffffffu, ls1, 2);
        l0r = l0r*sc0 + ls0;
        l1r = l1r*sc1 + ls1;

        #pragma unroll
        for (int nt=0;nt<16;nt++){
            O[nt][0] *= sc0; O[nt][1] *= sc0;
            O[nt][2] *= sc1; O[nt][3] *= sc1;
        }

        // ---- O += P @ V^T ----
        #pragma unroll
        for (int g=0; g<8; g++){
            #pragma unroll
            for (int ct=0; ct<8; ct++){
                uint32_t vb[4];
                ldm_x4(vb, vbase + (ct*16 + (lane & 7) + ((lane >> 4) << 3))*ROWV
                           + (g*16 + (((lane >> 3) & 1) << 3))*2);
                mma16816(O[ct*2],   pa[g], vb[0], vb[1]);
                mma16816(O[ct*2+1], pa[g], vb[2], vb[3]);
            }
        }
    }

    // ---- epilogue: /l, transpose [c][i] via smem, fused residual ----
    __syncthreads();
    float linv0 = 1.0f / l0r, linv1 = 1.0f / l1r;
    int r0 = wid*16 + (lane >> 2);
    #pragma unroll
    for (int nt=0; nt<16; nt++){
        int c0 = nt*8 + 2*(lane & 3);
        smf[(OFF_EPI>>2) + c0*132 + r0]         = O[nt][0]*linv0;
        smf[(OFF_EPI>>2) + (c0+1)*132 + r0]     = O[nt][1]*linv0;
        smf[(OFF_EPI>>2) + c0*132 + r0 + 8]     = O[nt][2]*linv1;
        smf[(OFF_EPI>>2) + (c0+1)*132 + r0 + 8] = O[nt][3]*linv1;
    }
    __syncthreads();
    #pragma unroll
    for (int e=0; e<16; e++){
        int idx = e*256 + tid;
        int cl = idx >> 5, i4 = (idx & 31)*4;
        float4 ov = *(float4*)&smf[(OFF_EPI>>2) + cl*132 + i4];
        int gc = ch*128 + cl;
        size_t ga = (size_t)gc*NPIX + i0 + i4;
        float4 xv = *(const float4*)&xin[ga];
        float4 dv = *(const float4*)&db[ga];
        float4 o;
        o.x = xv.x + gamma*(ov.x + dv.x);
        o.y = xv.y + gamma*(ov.y + dv.y);
        o.z = xv.z + gamma*(ov.z + dv.z);
        o.w = xv.w + gamma*(ov.w + dv.w);
        *(float4*)&outp[ga] = o;
    }
}

// ---------------- launch --------------------------------------------------------------
extern "C" void kernel_launch(void* const* d_in, const int* in_sizes, int n_in,
                              void* d_out, int out_size)
{
    const float* x1  = (const float*)d_in[0];
    const float* x2  = (const float*)d_in[1];
    const float* wq1 = (const float*)d_in[2];
    const float* bq1 = (const float*)d_in[3];
    const float* wk1 = (const float*)d_in[4];
    const float* bk1 = (const float*)d_in[5];
    const float* wv1 = (const float*)d_in[6];
    const float* bv1 = (const float*)d_in[7];
    const float* wq2 = (const float*)d_in[8];
    const float* bq2 = (const float*)d_in[9];
    const float* wk2 = (const float*)d_in[10];
    const float* bk2 = (const float*)d_in[11];
    const float* wv2 = (const float*)d_in[12];
    const float* bv2 = (const float*)d_in[13];
    const float* wd1 = (const float*)d_in[14];
    const float* bd1 = (const float*)d_in[15];
    const float* wd3 = (const float*)d_in[16];
    const float* bd3 = (const float*)d_in[17];
    const float* g1  = (const float*)d_in[18];
    const float* g2  = (const float*)d_in[19];
    float* out = (float*)d_out;

    cudaFuncSetAttribute(mma_gemm_kernel<0>,
                         cudaFuncAttributeMaxDynamicSharedMemorySize, MMA_SMEM);
    cudaFuncSetAttribute(mma_gemm_kernel<1>,
                         cudaFuncAttributeMaxDynamicSharedMemorySize, MMA_SMEM);
    cudaFuncSetAttribute(qk_mma_kernel,
                         cudaFuncAttributeMaxDynamicSharedMemorySize, QK_SMEM);
    cudaFuncSetAttribute(flash_kernel,
                         cudaFuncAttributeMaxDynamicSharedMemorySize, FLASH_SMEM);

    dim3 blk(256);

    // weight prep (single kernel) + im2col
    prep_all_kernel<<<(CH*KC + 255)/256, blk>>>(wv1, wv2, wd1, wd3, bd1, bd3,
                                                wq1, wk1, wq2, wk2, bq1, bk1, bq2, bk2);
    im2col_kernel<<<dim3(64, 8, 8), blk>>>(x1, x2);

    // q+k projections via HMMA -> fp16 [i][d]
    qk_mma_kernel<<<dim3(32, 1, 8), blk, QK_SMEM>>>();

    // v projections (fp16 [c][i])
    mma_gemm_kernel<0><<<dim3(32,2,8), blk, MMA_SMEM>>>(bv1, bv2);
    // merged residual branch: conv1x1(wd1) + conv3x3(wd3), K=2304 GEMM
    mma_gemm_kernel<1><<<dim3(32,2,8), blk, MMA_SMEM>>>(bv1, bv2);

    // fused flash attention + final epilogue
    flash_kernel<<<dim3(32,2,8), blk, FLASH_SMEM>>>(x1, x2, g1, g2, out);
}

// round 17
// speedup vs baseline: 6.7502x; 1.0468x over previous
#include <cuda_runtime.h>
#include <cuda_fp16.h>
#include <cstdint>
#include <cstddef>

#define BATCH 4
#define CH    256
#define NPIX  4096
#define HWD   64
#define KC    2304   // 9*256 im2col K

// ---------------- scratch (static __device__ — no allocation allowed) ----------------
__device__ __align__(128) __half g_xcolT[(size_t)8*NPIX*KC];      // [which*4+b][i][kc]
__device__ __align__(128) __half g_vh[(size_t)8*CH*NPIX];         // v projections fp16 [z][c][i]
__device__ __align__(128) float  g_db[(size_t)8*CH*NPIX];         // merged residual branch
__device__ __align__(128) __half g_qh[(size_t)8*NPIX*32];         // q fp16 [z][i][d]
__device__ __align__(128) __half g_kh[(size_t)8*NPIX*32];         // k fp16 [z][i][d]
__device__ __align__(128) __half g_wvh[2*CH*CH];                  // wv1|wv2 fp16
__device__ __align__(128) __half g_wmh[CH*KC];                    // merged wd3(+wd1 center) fp16
__device__ __align__(128) __half g_wqkh[2*64*CH];                 // [which][wq(32);wk(32)][256]
__device__ float g_bm[CH];                                        // bd1+bd3
__device__ float g_bqk[2*64];                                     // [which][bq;bk]

// ======================= warp-MMA helpers (compute_103-safe PTX) =======================
__device__ __forceinline__ uint32_t smem_to_u32(const void* p) {
    uint32_t a;
    asm("{ .reg .u64 t; cvta.to.shared.u64 t, %1; cvt.u32.u64 %0, t; }" : "=r"(a) : "l"(p));
    return a;
}
__device__ __forceinline__ void ldm_x4(uint32_t r[4], uint32_t addr) {
    asm volatile("ldmatrix.sync.aligned.m8n8.x4.shared.b16 {%0,%1,%2,%3}, [%4];"
                 : "=r"(r[0]), "=r"(r[1]), "=r"(r[2]), "=r"(r[3]) : "r"(addr));
}
__device__ __forceinline__ void mma16816(float c[4], const uint32_t a[4],
                                         uint32_t b0, uint32_t b1) {
    asm volatile("mma.sync.aligned.m16n8k16.row.col.f32.f16.f16.f32 "
                 "{%0,%1,%2,%3}, {%4,%5,%6,%7}, {%8,%9}, {%0,%1,%2,%3};"
                 : "+f"(c[0]), "+f"(c[1]), "+f"(c[2]), "+f"(c[3])
                 : "r"(a[0]), "r"(a[1]), "r"(a[2]), "r"(a[3]), "r"(b0), "r"(b1));
}
__device__ __forceinline__ void cp16(uint32_t saddr, const void* g) {
    asm volatile("cp.async.cg.shared.global [%0], [%1], 16;" :: "r"(saddr), "l"(g));
}
#define CP_COMMIT() asm volatile("cp.async.commit_group;" ::: "memory")
#define CP_WAIT(n)  asm volatile("cp.async.wait_group %0;" :: "n"(n) : "memory")

// MUFU exp2 (~2^-22 rel err, 1 instr)
__device__ __forceinline__ float ex2f(float x) {
    float y;
    asm("ex2.approx.ftz.f32 %0, %1;" : "=f"(y) : "f"(x));
    return y;
}
#define L2E 1.4426950408889634f

// ---------------- unified weight prep -------------------------------------------------
__global__ void prep_all_kernel(const float* __restrict__ wv1, const float* __restrict__ wv2,
                                const float* __restrict__ wd1, const float* __restrict__ wd3,
                                const float* __restrict__ bd1, const float* __restrict__ bd3,
                                const float* __restrict__ wq1, const float* __restrict__ wk1,
                                const float* __restrict__ wq2, const float* __restrict__ wk2,
                                const float* __restrict__ bq1, const float* __restrict__ bk1,
                                const float* __restrict__ bq2, const float* __restrict__ bk2)
{
    int idx = blockIdx.x*256 + threadIdx.x;
    if (idx < CH*KC) {
        int o = idx / KC, kc = idx % KC, kk = kc >> 8, c = kc & 255;
        float v = wd3[((size_t)o*CH + c)*9 + kk];
        if (kk == 4) v += wd1[(size_t)o*CH + c];
        g_wmh[idx] = __float2half_rn(v);
    }
    if (idx < 2*CH*CH) {
        int w = idx >> 16, r = idx & 65535;
        g_wvh[idx] = __float2half_rn((w ? wv2 : wv1)[r]);
    }
    if (idx < 2*64*CH) {
        int w = idx / (64*CH), rem = idx % (64*CH), r = rem / CH, c = rem % CH;
        const float* src = (r < 32) ? (w ? wq2 : wq1) : (w ? wk2 : wk1);
        int rr = r & 31;
        g_wqkh[idx] = __float2half_rn(src[(size_t)rr*CH + c]);
    }
    if (idx < CH) g_bm[idx] = bd1[idx] + bd3[idx];
    if (idx < 2*64) {
        int w = idx >> 6, r = idx & 63;
        const float* src = (r < 32) ? (w ? bq2 : bq1) : (w ? bk2 : bk1);
        g_bqk[idx] = src[r & 31];
    }
}

// ---------------- im2col -> fp16 [i][kc] transposed -----------------------------------
__global__ __launch_bounds__(256)
void im2col_kernel(const float* __restrict__ x1, const float* __restrict__ x2)
{
    __shared__ float sx[32][3*66];
    const int tid = threadIdx.x;
    const int yrow = blockIdx.x;
    const int c0 = blockIdx.y * 32;
    const int z = blockIdx.z;
    const int which = z >> 2, b = z & 3;
    const float* x = (which ? x2 : x1) + (size_t)b*CH*NPIX;

    for (int idx = tid; idx < 32*198; idx += 256) {
        int c = idx / 198, rem = idx % 198, r = rem / 66, xx = rem % 66;
        int yy = yrow + r - 1, col = xx - 1;
        float v = 0.f;
        if (yy >= 0 && yy < HWD && col >= 0 && col < HWD)
            v = x[(size_t)(c0+c)*NPIX + yy*HWD + col];
        sx[c][r*66 + xx] = v;
    }
    __syncthreads();
    __half* outp = g_xcolT + (size_t)z*NPIX*KC;
    for (int idx = tid; idx < 64*9*32; idx += 256) {
        int c = idx & 31, kk = (idx >> 5) % 9, i = idx / 288;
        int dy = kk / 3, dx = kk % 3;
        float v = sx[c][dy*66 + i + dx];
        outp[(size_t)(yrow*HWD + i)*KC + kk*256 + c0 + c] = __float2half_rn(v);
    }
}

// ---------------- warp-MMA f16 GEMM (v proj / residual branch), 3-stage ---------------
#define BKC 64
#define ROWB 144
#define ATILE_B (128*ROWB)
#define STAGE_B (2*ATILE_B)
#define MMA_SMEM (3*STAGE_B)

// MODE 0: v projection (out fp16 + bias, layout [c][i]) ; MODE 1: residual (fp32 + bias)
template<int MODE>
__global__ __launch_bounds__(256)
void mma_gemm_kernel(const float* __restrict__ bv1, const float* __restrict__ bv2)
{
    extern __shared__ char smem[];
    uint32_t sb = smem_to_u32(smem);
    const int tid = threadIdx.x, wid = tid >> 5, lane = tid & 31;
    const int warp_m = wid & 3, warp_n = wid >> 2;
    const int z = blockIdx.z, which = z >> 2;
    const int m0 = blockIdx.y*128, n0 = blockIdx.x*128;

    const __half* A; const __half* B;
    int lda, ldb, kstartB, nch;
    const float* bias; float* outf = nullptr; __half* outh = nullptr;

    if (MODE == 0) {
        A = g_wvh + (size_t)which*CH*CH; lda = CH;
        B = g_xcolT + (size_t)z*NPIX*KC; ldb = KC;
        kstartB = 1024; nch = 4;
        bias = which ? bv2 : bv1;
        outh = g_vh + (size_t)z*CH*NPIX;
    } else {
        A = g_wmh; lda = KC;
        B = g_xcolT + (size_t)z*NPIX*KC; ldb = KC;
        kstartB = 0; nch = KC/BKC;
        bias = g_bm;
        outf = g_db + (size_t)z*CH*NPIX;
    }

    float acc[2][8][4];
    #pragma unroll
    for (int i=0;i<2;i++)
        #pragma unroll
        for (int j=0;j<8;j++)
            #pragma unroll
            for (int q=0;q<4;q++) acc[i][j][q]=0.f;

    auto load_stage = [&](int c, int s) {
        uint32_t base = sb + (uint32_t)s*STAGE_B;
        int kA = c*BKC, kB = kstartB + c*BKC;
        #pragma unroll
        for (int q = 0; q < 4; q++) {
            int idx = q*256 + tid;
            int row = idx >> 3, seg = idx & 7;
            cp16(base + (uint32_t)(row*ROWB + seg*16), A + (size_t)(m0+row)*lda + kA + seg*8);
            cp16(base + ATILE_B + (uint32_t)(row*ROWB + seg*16), B + (size_t)(n0+row)*ldb + kB + seg*8);
        }
        CP_COMMIT();
    };

    load_stage(0, 0);
    load_stage(1, 1);
    for (int c = 0; c < nch; c++) {
        if (c+1 < nch) { CP_WAIT(1); } else { CP_WAIT(0); }
        __syncthreads();
        if (c+2 < nch) load_stage(c+2, (c+2)%3);
        uint32_t as = sb + (uint32_t)(c%3)*STAGE_B;
        uint32_t bs = as + ATILE_B;
        #pragma unroll
        for (int ks = 0; ks < BKC/16; ks++) {
            uint32_t af[2][4], bf[4][4];
            #pragma unroll
            for (int mt=0; mt<2; mt++)
                ldm_x4(af[mt], as + (warp_m*32 + mt*16 + (lane & 15))*ROWB
                               + (ks*16 + ((lane >> 4) << 3))*2);
            #pragma unroll
            for (int np=0; np<4; np++)
                ldm_x4(bf[np], bs + (warp_n*64 + np*16 + (lane & 7) + ((lane >> 4) << 3))*ROWB
                               + (ks*16 + (((lane >> 3) & 1) << 3))*2);
            #pragma unroll
            for (int mt=0; mt<2; mt++)
                #pragma unroll
                for (int nt=0; nt<8; nt++)
                    mma16816(acc[mt][nt], af[mt], bf[nt>>1][(nt&1)*2], bf[nt>>1][(nt&1)*2+1]);
        }
    }

    #pragma unroll
    for (int mt=0; mt<2; mt++) {
        #pragma unroll
        for (int hf=0; hf<2; hf++) {
            int m = m0 + warp_m*32 + mt*16 + (lane >> 2) + hf*8;
            float bsv = __ldg(&bias[m]);
            #pragma unroll
            for (int nt=0; nt<8; nt++) {
                int n = n0 + warp_n*64 + nt*8 + 2*(lane & 3);
                float v0 = acc[mt][nt][hf*2+0], v1 = acc[mt][nt][hf*2+1];
                size_t ga = (size_t)m*NPIX + n;
                if (MODE == 0) *(__half2*)&outh[ga] = __floats2half2_rn(v0 + bsv, v1 + bsv);
                else { float2 o; o.x = v0 + bsv; o.y = v1 + bsv; *(float2*)&outf[ga] = o; }
            }
        }
    }
}

// ---------------- q+k projection via HMMA: [64 d-rows] x [4096 i], K=256 --------------
#define QK_ATILE (64*ROWB)
#define QK_BTILE (128*ROWB)
#define QK_STAGE (QK_ATILE + QK_BTILE)
#define QK_SMEM  (3*QK_STAGE)

__global__ __launch_bounds__(256)
void qk_mma_kernel()
{
    extern __shared__ char smem[];
    uint32_t sb = smem_to_u32(smem);
    const int tid = threadIdx.x, wid = tid >> 5, lane = tid & 31;
    const int wm = wid & 1, wn = wid >> 1;
    const int z = blockIdx.z, which = z >> 2;
    const int n0 = blockIdx.x*128;

    const __half* A = g_wqkh + (size_t)which*64*CH;
    const __half* B = g_xcolT + (size_t)z*NPIX*KC;

    float acc[2][4][4];
    #pragma unroll
    for (int i=0;i<2;i++)
        #pragma unroll
        for (int j=0;j<4;j++)
            #pragma unroll
            for (int q=0;q<4;q++) acc[i][j][q]=0.f;

    auto load_stage = [&](int c, int s) {
        uint32_t base = sb + (uint32_t)s*QK_STAGE;
        int kA = c*BKC, kB = 1024 + c*BKC;
        #pragma unroll
        for (int q = 0; q < 2; q++) {
            int idx = q*256 + tid, row = idx >> 3, seg = idx & 7;
            cp16(base + (uint32_t)(row*ROWB + seg*16), A + (size_t)row*CH + kA + seg*8);
        }
        #pragma unroll
        for (int q = 0; q < 4; q++) {
            int idx = q*256 + tid, row = idx >> 3, seg = idx & 7;
            cp16(base + QK_ATILE + (uint32_t)(row*ROWB + seg*16),
                 B + (size_t)(n0+row)*KC + kB + seg*8);
        }
        CP_COMMIT();
    };

    load_stage(0, 0);
    load_stage(1, 1);
    for (int c = 0; c < 4; c++) {
        if (c+1 < 4) { CP_WAIT(1); } else { CP_WAIT(0); }
        __syncthreads();
        if (c+2 < 4) load_stage(c+2, (c+2)%3);
        uint32_t as = sb + (uint32_t)(c%3)*QK_STAGE;
        uint32_t bs = as + QK_ATILE;
        #pragma unroll
        for (int ks = 0; ks < 4; ks++) {
            uint32_t af[2][4], bf[2][4];
            #pragma unroll
            for (int mt=0; mt<2; mt++)
                ldm_x4(af[mt], as + (wm*32 + mt*16 + (lane & 15))*ROWB
                               + (ks*16 + ((lane >> 4) << 3))*2);
            #pragma unroll
            for (int np=0; np<2; np++)
                ldm_x4(bf[np], bs + (wn*32 + np*16 + (lane & 7) + ((lane >> 4) << 3))*ROWB
                               + (ks*16 + (((lane >> 3) & 1) << 3))*2);
            #pragma unroll
            for (int mt=0; mt<2; mt++)
                #pragma unroll
                for (int nt=0; nt<4; nt++)
                    mma16816(acc[mt][nt], af[mt], bf[nt>>1][(nt&1)*2], bf[nt>>1][(nt&1)*2+1]);
        }
    }

    __half* qdst = g_qh + (size_t)z*NPIX*32;
    __half* kdst = g_kh + (size_t)z*NPIX*32;
    #pragma unroll
    for (int mt=0; mt<2; mt++) {
        #pragma unroll
        for (int hf=0; hf<2; hf++) {
            int m = wm*32 + mt*16 + (lane >> 2) + hf*8;
            float bsv = __ldg(&g_bqk[which*64 + m]);
            __half* dst = (m < 32) ? qdst : kdst;
            int od = m & 31;
            #pragma unroll
            for (int nt=0; nt<4; nt++) {
                int i = n0 + wn*32 + nt*8 + 2*(lane & 3);
                dst[(size_t)i*32 + od]     = __float2half_rn(acc[mt][nt][hf*2+0] + bsv);
                dst[(size_t)(i+1)*32 + od] = __float2half_rn(acc[mt][nt][hf*2+1] + bsv);
            }
        }
    }
}

// ---------------- flash attention (FA2, 2 CTAs/SM) + fused epilogue -------------------
// grid (32 i-tiles, 2 c-halves, 8 z). 256 thr, 8 warps; warp w owns rows w*16..w*16+15.
// j-tile processed as two 64-wide sub-halves to keep regs <=128 (2 CTAs/SM fills
// tensor-pipe bubbles during the serial softmax chain).
#define ROWQ 80
#define ROWV 272
#define OFF_Q   0
#define OFF_K   10240
#define OFF_V   30720
#define OFF_EPI 10240
#define FLASH_SMEM 100352

__global__ __launch_bounds__(256, 2)
void flash_kernel(const float* __restrict__ x1, const float* __restrict__ x2,
                  const float* __restrict__ g1, const float* __restrict__ g2,
                  float* __restrict__ outbuf)
{
    extern __shared__ char smem[];
    uint32_t sb = smem_to_u32(smem);
    float* smf = (float*)smem;
    const int tid = threadIdx.x, wid = tid >> 5, lane = tid & 31;
    const int ch = blockIdx.y, z = blockIdx.z;
    const int which = z >> 2, b = z & 3;
    const int i0 = blockIdx.x * 128;
    const int zo = (1 - which)*BATCH + b;   // source of k and v

    const __half* qg = g_qh + (size_t)z*NPIX*32;
    const __half* kg = g_kh + (size_t)zo*NPIX*32;
    const __half* vg = g_vh + ((size_t)zo*CH + ch*128)*NPIX;
    const float* xin = (which ? x2 : x1) + (size_t)b*CH*NPIX;
    const float* db  = g_db + (size_t)z*CH*NPIX;
    const float gamma = __ldg(which ? g2 : g1);
    float* outp = outbuf + (size_t)which*(BATCH*CH*NPIX) + (size_t)b*CH*NPIX;

    float O[16][4];
    #pragma unroll
    for (int nt=0;nt<16;nt++)
        #pragma unroll
        for (int q=0;q<4;q++) O[nt][q]=0.f;
    float m0r = -1e30f, m1r = -1e30f, l0r = 0.f, l1r = 0.f;

    // prefetch: Q + tile 0 (same group)
    #pragma unroll
    for (int qq=0; qq<2; qq++){
        int idx = qq*256 + tid, row = idx >> 2, seg = idx & 3;
        cp16(sb + OFF_Q + row*ROWQ + seg*16, qg + (size_t)(i0+row)*32 + seg*8);
    }
    auto load_tile = [&](int t, int s){
        int j0 = t*128;
        uint32_t kb = sb + OFF_K + s*10240;
        uint32_t vbb = sb + OFF_V + s*34816;
        #pragma unroll
        for (int qq=0; qq<2; qq++){
            int idx = qq*256 + tid, row = idx >> 2, seg = idx & 3;
            cp16(kb + row*ROWQ + seg*16, kg + (size_t)(j0+row)*32 + seg*8);
        }
        #pragma unroll
        for (int qq=0; qq<8; qq++){
            int idx = qq*256 + tid, row = idx >> 4, seg = idx & 15;
            cp16(vbb + row*ROWV + seg*16, vg + (size_t)row*NPIX + j0 + seg*8);
        }
        CP_COMMIT();
    };
    load_tile(0, 0);
    CP_WAIT(0);
    __syncthreads();

    for (int t = 0; t < 32; t++) {
        int s = t & 1;
        if (t > 0) {
            CP_WAIT(0);
            __syncthreads();
        }
        if (t+1 < 32) load_tile(t+1, s^1);

        uint32_t kbase = sb + OFF_K + s*10240;
        uint32_t vbase = sb + OFF_V + s*34816;

        // per-tile Q fragments (reloaded to limit persistent regs)
        uint32_t qf[2][4];
        #pragma unroll
        for (int ks=0; ks<2; ks++)
            ldm_x4(qf[ks], sb + OFF_Q + (wid*16 + (lane & 15))*ROWQ
                           + (ks*16 + ((lane >> 4) << 3))*2);

        #pragma unroll
        for (int jh = 0; jh < 2; jh++) {
            // ---- S = q @ k^T for 64-j sub-half ----
            float S[8][4];
            #pragma unroll
            for (int nt=0;nt<8;nt++)
                #pragma unroll
                for (int q=0;q<4;q++) S[nt][q]=0.f;
            #pragma unroll
            for (int ks=0; ks<2; ks++){
                #pragma unroll
                for (int jt=0; jt<4; jt++){
                    uint32_t bf[4];
                    ldm_x4(bf, kbase + (jh*64 + jt*16 + (lane & 7) + ((lane >> 4) << 3))*ROWQ
                               + (ks*16 + (((lane >> 3) & 1) << 3))*2);
                    mma16816(S[jt*2],   qf[ks], bf[0], bf[1]);
                    mma16816(S[jt*2+1], qf[ks], bf[2], bf[3]);
                }
            }

            // ---- warp-local online softmax over 64 cols ----
            float mt0 = -1e30f, mt1 = -1e30f;
            #pragma unroll
            for (int nt=0;nt<8;nt++){
                mt0 = fmaxf(mt0, fmaxf(S[nt][0], S[nt][1]));
                mt1 = fmaxf(mt1, fmaxf(S[nt][2], S[nt][3]));
            }
            mt0 = fmaxf(mt0, __shfl_xor_sync(0xffffffffu, mt0, 1));
            mt0 = fmaxf(mt0, __shfl_xor_sync(0xffffffffu, mt0, 2));
            mt1 = fmaxf(mt1, __shfl_xor_sync(0xffffffffu, mt1, 1));
            mt1 = fmaxf(mt1, __shfl_xor_sync(0xffffffffu, mt1, 2));
            float mn0 = fmaxf(m0r, mt0), mn1 = fmaxf(m1r, mt1);
            float sc0 = ex2f((m0r - mn0)*L2E), sc1 = ex2f((m1r - mn1)*L2E);
            m0r = mn0; m1r = mn1;
            float mnl0 = mn0*L2E, mnl1 = mn1*L2E;

            float ls0 = 0.f, ls1 = 0.f;
            uint32_t pa[4][4];
            #pragma unroll
            for (int g=0; g<4; g++){
                float e00 = ex2f(fmaf(S[2*g][0],   L2E, -mnl0));
                float e01 = ex2f(fmaf(S[2*g][1],   L2E, -mnl0));
                float e02 = ex2f(fmaf(S[2*g][2],   L2E, -mnl1));
                float e03 = ex2f(fmaf(S[2*g][3],   L2E, -mnl1));
                float e10 = ex2f(fmaf(S[2*g+1][0], L2E, -mnl0));
                float e11 = ex2f(fmaf(S[2*g+1][1], L2E, -mnl0));
                float e12 = ex2f(fmaf(S[2*g+1][2], L2E, -mnl1));
                float e13 = ex2f(fmaf(S[2*g+1][3], L2E, -mnl1));
                ls0 += e00 + e01 + e10 + e11;
                ls1 += e02 + e03 + e12 + e13;
                __half2 h0 = __floats2half2_rn(e00, e01);
                __half2 h1 = __floats2half2_rn(e02, e03);
                __half2 h2 = __floats2half2_rn(e10, e11);
                __half2 h3 = __floats2half2_rn(e12, e13);
                pa[g][0] = *(uint32_t*)&h0;
                pa[g][1] = *(uint32_t*)&h1;
                pa[g][2] = *(uint32_t*)&h2;
                pa[g][3] = *(uint32_t*)&h3;
            }
            ls0 += __shfl_xor_sync(0xffffffffu, ls0, 1);
            ls0 += __shfl_xor_sync(0xffffffffu, ls0, 2);
            ls1 += __shfl_xor_sync(0xffffffffu, ls1, 1);
            ls1 += __shfl_xor_sync(0xffffffffu, ls1, 2);
            l0r = l0r*sc0 + ls0;
            l1r = l1r*sc1 + ls1;

            #pragma unroll
            for (int nt=0;nt<16;nt++){
                O[nt][0] *= sc0; O[nt][1] *= sc0;
                O[nt][2] *= sc1; O[nt][3] *= sc1;
            }

            // ---- O += P @ V^T for this sub-half ----
            #pragma unroll
            for (int g=0; g<4; g++){
                #pragma unroll
                for (int ct=0; ct<8; ct++){
                    uint32_t vb[4];
                    ldm_x4(vb, vbase + (ct*16 + (lane & 7) + ((lane >> 4) << 3))*ROWV
                               + (jh*64 + g*16 + (((lane >> 3) & 1) << 3))*2);
                    mma16816(O[ct*2],   pa[g], vb[0], vb[1]);
                    mma16816(O[ct*2+1], pa[g], vb[2], vb[3]);
                }
            }
        }
    }

    // ---- epilogue: /l, transpose [c][i] via smem, fused residual ----
    __syncthreads();
    float linv0 = 1.0f / l0r, linv1 = 1.0f / l1r;
    int r0 = wid*16 + (lane >> 2);
    #pragma unroll
    for (int nt=0; nt<16; nt++){
        int c0 = nt*8 + 2*(lane & 3);
        smf[(OFF_EPI>>2) + c0*132 + r0]         = O[nt][0]*linv0;
        smf[(OFF_EPI>>2) + (c0+1)*132 + r0]     = O[nt][1]*linv0;
        smf[(OFF_EPI>>2) + c0*132 + r0 + 8]     = O[nt][2]*linv1;
        smf[(OFF_EPI>>2) + (c0+1)*132 + r0 + 8] = O[nt][3]*linv1;
    }
    __syncthreads();
    #pragma unroll
    for (int e=0; e<16; e++){
        int idx = e*256 + tid;
        int cl = idx >> 5, i4 = (idx & 31)*4;
        float4 ov = *(float4*)&smf[(OFF_EPI>>2) + cl*132 + i4];
        int gc = ch*128 + cl;
        size_t ga = (size_t)gc*NPIX + i0 + i4;
        float4 xv = *(const float4*)&xin[ga];
        float4 dv = *(const float4*)&db[ga];
        float4 o;
        o.x = xv.x + gamma*(ov.x + dv.x);
        o.y = xv.y + gamma*(ov.y + dv.y);
        o.z = xv.z + gamma*(ov.z + dv.z);
        o.w = xv.w + gamma*(ov.w + dv.w);
        *(float4*)&outp[ga] = o;
    }
}

// ---------------- launch --------------------------------------------------------------
extern "C" void kernel_launch(void* const* d_in, const int* in_sizes, int n_in,
                              void* d_out, int out_size)
{
    const float* x1  = (const float*)d_in[0];
    const float* x2  = (const float*)d_in[1];
    const float* wq1 = (const float*)d_in[2];
    const float* bq1 = (const float*)d_in[3];
    const float* wk1 = (const float*)d_in[4];
    const float* bk1 = (const float*)d_in[5];
    const float* wv1 = (const float*)d_in[6];
    const float* bv1 = (const float*)d_in[7];
    const float* wq2 = (const float*)d_in[8];
    const float* bq2 = (const float*)d_in[9];
    const float* wk2 = (const float*)d_in[10];
    const float* bk2 = (const float*)d_in[11];
    const float* wv2 = (const float*)d_in[12];
    const float* bv2 = (const float*)d_in[13];
    const float* wd1 = (const float*)d_in[14];
    const float* bd1 = (const float*)d_in[15];
    const float* wd3 = (const float*)d_in[16];
    const float* bd3 = (const float*)d_in[17];
    const float* g1  = (const float*)d_in[18];
    const float* g2  = (const float*)d_in[19];
    float* out = (float*)d_out;

    cudaFuncSetAttribute(mma_gemm_kernel<0>,
                         cudaFuncAttributeMaxDynamicSharedMemorySize, MMA_SMEM);
    cudaFuncSetAttribute(mma_gemm_kernel<1>,
                         cudaFuncAttributeMaxDynamicSharedMemorySize, MMA_SMEM);
    cudaFuncSetAttribute(qk_mma_kernel,
                         cudaFuncAttributeMaxDynamicSharedMemorySize, QK_SMEM);
    cudaFuncSetAttribute(flash_kernel,
                         cudaFuncAttributeMaxDynamicSharedMemorySize, FLASH_SMEM);

    dim3 blk(256);

    // weight prep (single kernel) + im2col
    prep_all_kernel<<<(CH*KC + 255)/256, blk>>>(wv1, wv2, wd1, wd3, bd1, bd3,
                                                wq1, wk1, wq2, wk2, bq1, bk1, bq2, bk2);
    im2col_kernel<<<dim3(64, 8, 8), blk>>>(x1, x2);

    // q+k projections via HMMA -> fp16 [i][d]
    qk_mma_kernel<<<dim3(32, 1, 8), blk, QK_SMEM>>>();

    // v projections (fp16 [c][i])
    mma_gemm_kernel<0><<<dim3(32,2,8), blk, MMA_SMEM>>>(bv1, bv2);
    // merged residual branch: conv1x1(wd1) + conv3x3(wd3), K=2304 GEMM
    mma_gemm_kernel<1><<<dim3(32,2,8), blk, MMA_SMEM>>>(bv1, bv2);

    // fused flash attention (2 CTAs/SM) + final epilogue
    flash_kernel<<<dim3(32,2,8), blk, FLASH_SMEM>>>(x1, x2, g1, g2, out);
}